// round 1
// baseline (speedup 1.0000x reference)
#include <cuda_runtime.h>
#include <math.h>

// Problem constants
#define T_TOK 8192          // B*S tokens
#define D_DIM 1024          // embedding
#define FF_DIM 2048         // expert hidden
#define E_NUM 8             // experts
#define K_TOP 2             // top-k
#define NSLOT (T_TOK * K_TOP)
#define W1_LD (E_NUM * FF_DIM)   // 16384, w1 is [D, E*FF]

// ---------------- scratch (device globals; no allocation allowed) -------------
__device__ float g_h[(size_t)NSLOT * FF_DIM];   // 134 MB intermediate gelu(x@W1)
__device__ int   g_sel[NSLOT];                  // selected expert per (token,k)
__device__ float g_wsel[NSLOT];                 // normalized top-k weight
__device__ int   g_slot_token[NSLOT];           // expert-grouped token index
__device__ float g_slot_w[NSLOT];               // expert-grouped weight
__device__ int   g_counts[E_NUM];
__device__ int   g_offsets[E_NUM];
__device__ int   g_fill[E_NUM];
__device__ float g_psum[E_NUM];
__device__ float g_zsum;

// ---------------- kernel 0: zero output ----------------
__global__ void zero_out_kernel(float* out, int n) {
    int idx = blockIdx.x * blockDim.x + threadIdx.x;
    int stride = gridDim.x * blockDim.x;
    for (int i = idx; i < n; i += stride) out[i] = 0.0f;
}

// ---------------- kernel 1: init accumulators ----------------
__global__ void init_kernel() {
    int t = threadIdx.x;
    if (t < E_NUM) {
        g_counts[t] = 0;
        g_fill[t]   = 0;
        g_psum[t]   = 0.0f;
    }
    if (t == 0) g_zsum = 0.0f;
}

// ---------------- kernel 2: router ----------------
// 1 warp per token; 8 warps (256 threads) per block; router_w cached in smem.
__global__ __launch_bounds__(256) void router_kernel(
    const float* __restrict__ x, const float* __restrict__ rw)
{
    __shared__ float s_rw[E_NUM * D_DIM];   // 32 KB
    __shared__ float sp[E_NUM];
    __shared__ int   sc[E_NUM];
    __shared__ float sz;

    int tid = threadIdx.x;
    for (int i = tid; i < E_NUM * D_DIM; i += 256) s_rw[i] = rw[i];
    if (tid < E_NUM) { sp[tid] = 0.0f; sc[tid] = 0; }
    if (tid == 0) sz = 0.0f;
    __syncthreads();

    int warp = tid >> 5;
    int lane = tid & 31;
    int t = blockIdx.x * 8 + warp;

    float acc[E_NUM];
#pragma unroll
    for (int e = 0; e < E_NUM; e++) acc[e] = 0.0f;

    const float* xr = x + (size_t)t * D_DIM;
    for (int d = lane; d < D_DIM; d += 32) {
        float xv = xr[d];
#pragma unroll
        for (int e = 0; e < E_NUM; e++) acc[e] += xv * s_rw[e * D_DIM + d];
    }
#pragma unroll
    for (int e = 0; e < E_NUM; e++) {
#pragma unroll
        for (int off = 16; off > 0; off >>= 1)
            acc[e] += __shfl_xor_sync(0xFFFFFFFF, acc[e], off);
    }

    if (lane == 0) {
        float m = acc[0];
#pragma unroll
        for (int e = 1; e < E_NUM; e++) m = fmaxf(m, acc[e]);
        float p[E_NUM], s = 0.0f;
#pragma unroll
        for (int e = 0; e < E_NUM; e++) { p[e] = expf(acc[e] - m); s += p[e]; }
        float inv = 1.0f / s;
        float lse = m + logf(s);

        int i1 = 0;
#pragma unroll
        for (int e = 1; e < E_NUM; e++) if (acc[e] > acc[i1]) i1 = e;
        int i2 = (i1 == 0) ? 1 : 0;
#pragma unroll
        for (int e = 0; e < E_NUM; e++)
            if (e != i1 && acc[e] > acc[i2]) i2 = e;

        float p1 = p[i1] * inv, p2 = p[i2] * inv;
        float winv = 1.0f / (p1 + p2);
        g_sel[2 * t]      = i1;
        g_wsel[2 * t]     = p1 * winv;
        g_sel[2 * t + 1]  = i2;
        g_wsel[2 * t + 1] = p2 * winv;

#pragma unroll
        for (int e = 0; e < E_NUM; e++) atomicAdd(&sp[e], p[e] * inv);
        atomicAdd(&sz, lse * lse);
        atomicAdd(&sc[i1], 1);
        atomicAdd(&sc[i2], 1);
    }
    __syncthreads();
    if (tid < E_NUM) {
        atomicAdd(&g_psum[tid], sp[tid]);
        atomicAdd(&g_counts[tid], sc[tid]);
    }
    if (tid == 0) atomicAdd(&g_zsum, sz);
}

// ---------------- kernel 3: finalize losses + offsets scan ----------------
__global__ void finalize_kernel(float* out, int out_size) {
    if (threadIdx.x == 0 && blockIdx.x == 0) {
        int off = 0;
        for (int e = 0; e < E_NUM; e++) { g_offsets[e] = off; off += g_counts[e]; }
        float z = g_zsum / (float)T_TOK;
        float lb = 0.0f;
        for (int e = 0; e < E_NUM; e++)
            lb += ((float)g_counts[e] / (float)(T_TOK * K_TOP)) *
                  (g_psum[e] / (float)T_TOK);
        lb *= (float)E_NUM;
        out[out_size - 2] = z;
        out[out_size - 1] = lb;
    }
}

// ---------------- kernel 4: scatter into expert groups ----------------
__global__ void scatter_kernel() {
    int s = blockIdx.x * blockDim.x + threadIdx.x;
    if (s >= NSLOT) return;
    int e = g_sel[s];
    int pos = g_offsets[e] + atomicAdd(&g_fill[e], 1);
    g_slot_token[pos] = s >> 1;
    g_slot_w[pos]     = g_wsel[s];
}

// ---------------- grouped SGEMM tiles: 128x128x8, 256 thr, 8x8 microtile ----
#define BM 128
#define BN 128
#define BK 8

__device__ __forceinline__ float gelu_exact(float v) {
    return 0.5f * v * (1.0f + erff(v * 0.70710678118654752f));
}

// GEMM1: h[row, n] = gelu( sum_d x[tok(row), d] * w1[d, e*FF + n] )
__global__ __launch_bounds__(256) void gemm1_kernel(
    const float* __restrict__ x, const float* __restrict__ w1)
{
    int e = blockIdx.z;
    int base = g_offsets[e];
    int cnt  = g_counts[e];
    int m0   = blockIdx.y * BM;
    if (m0 >= cnt) return;
    int n0   = blockIdx.x * BN;

    __shared__ float As[BK][BM];
    __shared__ float Bs[BK][BN];

    int tid = threadIdx.x;
    int ty = tid >> 4, tx = tid & 15;          // 16x16 thread grid
    int a_row = tid >> 1;                      // 0..127
    int a_col = (tid & 1) << 2;                // 0 or 4
    int b_row = tid >> 5;                      // 0..7
    int b_col = (tid & 31) << 2;               // 0..124

    // per-thread gathered A row
    int grow_a = base + m0 + a_row;
    bool a_valid = (m0 + a_row) < cnt;
    size_t a_off = 0;
    if (a_valid) a_off = (size_t)g_slot_token[grow_a] * D_DIM;

    const float* Bp = w1 + (size_t)e * FF_DIM + n0;   // (k,c): Bp[k*W1_LD + c]

    float accv[8][8];
#pragma unroll
    for (int i = 0; i < 8; i++)
#pragma unroll
        for (int j = 0; j < 8; j++) accv[i][j] = 0.0f;

    for (int kt = 0; kt < D_DIM; kt += BK) {
        float4 av = make_float4(0.f, 0.f, 0.f, 0.f);
        if (a_valid) av = *(const float4*)(x + a_off + kt + a_col);
        As[a_col + 0][a_row] = av.x;
        As[a_col + 1][a_row] = av.y;
        As[a_col + 2][a_row] = av.z;
        As[a_col + 3][a_row] = av.w;
        float4 bv = *(const float4*)(Bp + (size_t)(kt + b_row) * W1_LD + b_col);
        *(float4*)&Bs[b_row][b_col] = bv;
        __syncthreads();
#pragma unroll
        for (int kk = 0; kk < BK; kk++) {
            float a[8], b[8];
#pragma unroll
            for (int i = 0; i < 8; i++) a[i] = As[kk][ty * 8 + i];
#pragma unroll
            for (int j = 0; j < 8; j++) b[j] = Bs[kk][tx * 8 + j];
#pragma unroll
            for (int i = 0; i < 8; i++)
#pragma unroll
                for (int j = 0; j < 8; j++) accv[i][j] += a[i] * b[j];
        }
        __syncthreads();
    }

#pragma unroll
    for (int i = 0; i < 8; i++) {
        int mrow = m0 + ty * 8 + i;
        if (mrow < cnt) {
            size_t ho = (size_t)(base + mrow) * FF_DIM + n0 + tx * 8;
#pragma unroll
            for (int j = 0; j < 8; j++) g_h[ho + j] = gelu_exact(accv[i][j]);
        }
    }
}

// GEMM2: out[tok(row), n] += w(row) * sum_f h[row, f] * w2[(e*FF+f), n]
__global__ __launch_bounds__(256) void gemm2_kernel(
    const float* __restrict__ w2, float* __restrict__ out)
{
    int e = blockIdx.z;
    int base = g_offsets[e];
    int cnt  = g_counts[e];
    int m0   = blockIdx.y * BM;
    if (m0 >= cnt) return;
    int n0   = blockIdx.x * BN;

    __shared__ float As[BK][BM];
    __shared__ float Bs[BK][BN];

    int tid = threadIdx.x;
    int ty = tid >> 4, tx = tid & 15;
    int a_row = tid >> 1;
    int a_col = (tid & 1) << 2;
    int b_row = tid >> 5;
    int b_col = (tid & 31) << 2;

    int grow_a = base + m0 + a_row;
    bool a_valid = (m0 + a_row) < cnt;
    size_t a_off = (size_t)grow_a * FF_DIM;

    const float* Bp = w2 + (size_t)e * FF_DIM * D_DIM + n0;  // (f,c): Bp[f*D + c]

    float accv[8][8];
#pragma unroll
    for (int i = 0; i < 8; i++)
#pragma unroll
        for (int j = 0; j < 8; j++) accv[i][j] = 0.0f;

    for (int kt = 0; kt < FF_DIM; kt += BK) {
        float4 av = make_float4(0.f, 0.f, 0.f, 0.f);
        if (a_valid) av = *(const float4*)(g_h + a_off + kt + a_col);
        As[a_col + 0][a_row] = av.x;
        As[a_col + 1][a_row] = av.y;
        As[a_col + 2][a_row] = av.z;
        As[a_col + 3][a_row] = av.w;
        float4 bv = *(const float4*)(Bp + (size_t)(kt + b_row) * D_DIM + b_col);
        *(float4*)&Bs[b_row][b_col] = bv;
        __syncthreads();
#pragma unroll
        for (int kk = 0; kk < BK; kk++) {
            float a[8], b[8];
#pragma unroll
            for (int i = 0; i < 8; i++) a[i] = As[kk][ty * 8 + i];
#pragma unroll
            for (int j = 0; j < 8; j++) b[j] = Bs[kk][tx * 8 + j];
#pragma unroll
            for (int i = 0; i < 8; i++)
#pragma unroll
                for (int j = 0; j < 8; j++) accv[i][j] += a[i] * b[j];
        }
        __syncthreads();
    }

#pragma unroll
    for (int i = 0; i < 8; i++) {
        int mrow = m0 + ty * 8 + i;
        if (mrow < cnt) {
            int row = base + mrow;
            int tok = g_slot_token[row];
            float w = g_slot_w[row];
            float* op = out + (size_t)tok * D_DIM + n0 + tx * 8;
#pragma unroll
            for (int j = 0; j < 8; j++) atomicAdd(&op[j], w * accv[i][j]);
        }
    }
}

// ---------------- launcher ----------------
extern "C" void kernel_launch(void* const* d_in, const int* in_sizes, int n_in,
                              void* d_out, int out_size) {
    const float* x  = (const float*)d_in[0];
    const float* rw = (const float*)d_in[1];
    const float* w1 = (const float*)d_in[2];
    const float* w2 = (const float*)d_in[3];
    float* out = (float*)d_out;

    zero_out_kernel<<<1024, 256>>>(out, out_size);
    init_kernel<<<1, 64>>>();
    router_kernel<<<T_TOK / 8, 256>>>(x, rw);
    finalize_kernel<<<1, 32>>>(out, out_size);
    scatter_kernel<<<NSLOT / 256, 256>>>();

    dim3 g1(FF_DIM / BN, T_TOK / BM, E_NUM);   // (16, 64, 8)
    gemm1_kernel<<<g1, 256>>>(x, w1);
    dim3 g2(D_DIM / BN, T_TOK / BM, E_NUM);    // (8, 64, 8)
    gemm2_kernel<<<g2, 256>>>(w2, out);
}

// round 3
// speedup vs baseline: 1.1800x; 1.1800x over previous
#include <cuda_runtime.h>
#include <math.h>
#include <stdint.h>

// Problem constants
#define T_TOK 8192          // B*S tokens
#define D_DIM 1024          // embedding
#define FF_DIM 2048         // expert hidden
#define E_NUM 8             // experts
#define K_TOP 2             // top-k
#define NSLOT (T_TOK * K_TOP)
#define W1_LD (E_NUM * FF_DIM)   // w1 is [D, E*FF]

// ---------------- scratch (device globals; no allocation allowed) -------------
__device__ float g_h[(size_t)NSLOT * FF_DIM];   // 134 MB intermediate gelu(x@W1)
__device__ int   g_sel[NSLOT];
__device__ float g_wsel[NSLOT];
__device__ int   g_slot_token[NSLOT];
__device__ float g_slot_w[NSLOT];
__device__ int   g_counts[E_NUM];
__device__ int   g_offsets[E_NUM];
__device__ int   g_fill[E_NUM];
__device__ float g_psum[E_NUM];
__device__ float g_zsum;

// ---------------- kernel 0: zero output ----------------
__global__ void zero_out_kernel(float* out, int n) {
    int idx = blockIdx.x * blockDim.x + threadIdx.x;
    int stride = gridDim.x * blockDim.x;
    for (int i = idx; i < n; i += stride) out[i] = 0.0f;
}

// ---------------- kernel 1: init accumulators ----------------
__global__ void init_kernel() {
    int t = threadIdx.x;
    if (t < E_NUM) {
        g_counts[t] = 0;
        g_fill[t]   = 0;
        g_psum[t]   = 0.0f;
    }
    if (t == 0) g_zsum = 0.0f;
}

// ---------------- kernel 2: router ----------------
__global__ __launch_bounds__(256) void router_kernel(
    const float* __restrict__ x, const float* __restrict__ rw)
{
    __shared__ float s_rw[E_NUM * D_DIM];   // 32 KB
    __shared__ float sp[E_NUM];
    __shared__ int   sc[E_NUM];
    __shared__ float sz;

    int tid = threadIdx.x;
    for (int i = tid; i < E_NUM * D_DIM; i += 256) s_rw[i] = rw[i];
    if (tid < E_NUM) { sp[tid] = 0.0f; sc[tid] = 0; }
    if (tid == 0) sz = 0.0f;
    __syncthreads();

    int warp = tid >> 5;
    int lane = tid & 31;
    int t = blockIdx.x * 8 + warp;

    float acc[E_NUM];
#pragma unroll
    for (int e = 0; e < E_NUM; e++) acc[e] = 0.0f;

    const float* xr = x + (size_t)t * D_DIM;
    for (int d = lane; d < D_DIM; d += 32) {
        float xv = xr[d];
#pragma unroll
        for (int e = 0; e < E_NUM; e++) acc[e] += xv * s_rw[e * D_DIM + d];
    }
#pragma unroll
    for (int e = 0; e < E_NUM; e++) {
#pragma unroll
        for (int off = 16; off > 0; off >>= 1)
            acc[e] += __shfl_xor_sync(0xFFFFFFFF, acc[e], off);
    }

    if (lane == 0) {
        float m = acc[0];
#pragma unroll
        for (int e = 1; e < E_NUM; e++) m = fmaxf(m, acc[e]);
        float p[E_NUM], s = 0.0f;
#pragma unroll
        for (int e = 0; e < E_NUM; e++) { p[e] = expf(acc[e] - m); s += p[e]; }
        float inv = 1.0f / s;
        float lse = m + logf(s);

        int i1 = 0;
#pragma unroll
        for (int e = 1; e < E_NUM; e++) if (acc[e] > acc[i1]) i1 = e;
        int i2 = (i1 == 0) ? 1 : 0;
#pragma unroll
        for (int e = 0; e < E_NUM; e++)
            if (e != i1 && acc[e] > acc[i2]) i2 = e;

        float p1 = p[i1] * inv, p2 = p[i2] * inv;
        float winv = 1.0f / (p1 + p2);
        g_sel[2 * t]      = i1;
        g_wsel[2 * t]     = p1 * winv;
        g_sel[2 * t + 1]  = i2;
        g_wsel[2 * t + 1] = p2 * winv;

#pragma unroll
        for (int e = 0; e < E_NUM; e++) atomicAdd(&sp[e], p[e] * inv);
        atomicAdd(&sz, lse * lse);
        atomicAdd(&sc[i1], 1);
        atomicAdd(&sc[i2], 1);
    }
    __syncthreads();
    if (tid < E_NUM) {
        atomicAdd(&g_psum[tid], sp[tid]);
        atomicAdd(&g_counts[tid], sc[tid]);
    }
    if (tid == 0) atomicAdd(&g_zsum, sz);
}

// ---------------- kernel 3: finalize losses + offsets scan ----------------
__global__ void finalize_kernel(float* out, int out_size) {
    if (threadIdx.x == 0 && blockIdx.x == 0) {
        int off = 0;
        for (int e = 0; e < E_NUM; e++) { g_offsets[e] = off; off += g_counts[e]; }
        float z = g_zsum / (float)T_TOK;
        float lb = 0.0f;
        for (int e = 0; e < E_NUM; e++)
            lb += ((float)g_counts[e] / (float)(T_TOK * K_TOP)) *
                  (g_psum[e] / (float)T_TOK);
        lb *= (float)E_NUM;
        out[out_size - 2] = z;
        out[out_size - 1] = lb;
    }
}

// ---------------- kernel 4: scatter into expert groups ----------------
__global__ void scatter_kernel() {
    int s = blockIdx.x * blockDim.x + threadIdx.x;
    if (s >= NSLOT) return;
    int e = g_sel[s];
    int pos = g_offsets[e] + atomicAdd(&g_fill[e], 1);
    g_slot_token[pos] = s >> 1;
    g_slot_w[pos]     = g_wsel[s];
}

// ============== 3xTF32 tensor-core grouped GEMMs ===========================
// Tile: BM=128, BN=128, BK=16. 256 threads = 8 warps as 2(M) x 4(N).
// Operands split hi/lo at smem-store time; acc = ah*bh + ah*bl + al*bh.
#define BM 128
#define BN 128
#define BK 16
#define LDS_ (BM + 8)   // 136

__device__ __forceinline__ float gelu_exact(float v) {
    return 0.5f * v * (1.0f + erff(v * 0.70710678118654752f));
}

__device__ __forceinline__ void mma_tf32(
    float& c0, float& c1, float& c2, float& c3,
    uint32_t a0, uint32_t a1, uint32_t a2, uint32_t a3,
    uint32_t b0, uint32_t b1)
{
    asm volatile(
        "mma.sync.aligned.m16n8k8.row.col.f32.tf32.tf32.f32 "
        "{%0,%1,%2,%3}, {%4,%5,%6,%7}, {%8,%9}, {%0,%1,%2,%3};"
        : "+f"(c0), "+f"(c1), "+f"(c2), "+f"(c3)
        : "r"(a0), "r"(a1), "r"(a2), "r"(a3), "r"(b0), "r"(b1));
}

__device__ __forceinline__ void tf32_split(float v, float& hi, float& lo) {
    uint32_t h;
    asm("cvt.rna.tf32.f32 %0, %1;" : "=r"(h) : "f"(v));
    hi = __uint_as_float(h);
    float r = v - hi;
    uint32_t l;
    asm("cvt.rna.tf32.f32 %0, %1;" : "=r"(l) : "f"(r));
    lo = __uint_as_float(l);
}

// GEMM1: h[row, n] = gelu( sum_d x[tok(row), d] * w1[d, e*FF + n] )
__global__ __launch_bounds__(256) void gemm1_kernel(
    const float* __restrict__ x, const float* __restrict__ w1)
{
    int e = blockIdx.z;
    int base = g_offsets[e];
    int cnt  = g_counts[e];
    int m0   = blockIdx.y * BM;
    if (m0 >= cnt) return;
    int n0   = blockIdx.x * BN;

    __shared__ float Ah[BK][LDS_], Al[BK][LDS_];
    __shared__ float Bh[BK][LDS_], Bl[BK][LDS_];

    int tid  = threadIdx.x;
    int lane = tid & 31;
    int warp = tid >> 5;
    int group = lane >> 2;     // 0..7
    int tid4  = lane & 3;      // 0..3
    int wm = (warp & 1) * 64;  // warp M offset
    int wn = (warp >> 1) * 32; // warp N offset

    int am   = tid >> 1;
    int akb  = (tid & 1) * 8;
    int arow = base + m0 + am;
    int tok  = g_slot_token[arow < NSLOT ? arow : NSLOT - 1];
    const float* aptr = x + (size_t)tok * D_DIM + akb;

    int bkr = tid >> 4;
    int bnc = (tid & 15) * 8;
    const float* bptr = w1 + (size_t)e * FF_DIM + n0 + bnc;

    float acc[4][4][4];
#pragma unroll
    for (int mi = 0; mi < 4; mi++)
#pragma unroll
        for (int ni = 0; ni < 4; ni++)
#pragma unroll
            for (int c = 0; c < 4; c++) acc[mi][ni][c] = 0.0f;

    float4 pa0 = *(const float4*)(aptr + 0);
    float4 pa1 = *(const float4*)(aptr + 4);
    float4 pb0 = *(const float4*)(bptr + (size_t)bkr * W1_LD + 0);
    float4 pb1 = *(const float4*)(bptr + (size_t)bkr * W1_LD + 4);
    {
        float av[8] = {pa0.x, pa0.y, pa0.z, pa0.w, pa1.x, pa1.y, pa1.z, pa1.w};
        float bv[8] = {pb0.x, pb0.y, pb0.z, pb0.w, pb1.x, pb1.y, pb1.z, pb1.w};
#pragma unroll
        for (int q = 0; q < 8; q++) {
            tf32_split(av[q], Ah[akb + q][am], Al[akb + q][am]);
            tf32_split(bv[q], Bh[bkr][bnc + q], Bl[bkr][bnc + q]);
        }
    }
    __syncthreads();

    for (int kt = 0; kt < D_DIM; kt += BK) {
        bool more = (kt + BK) < D_DIM;
        if (more) {
            pa0 = *(const float4*)(aptr + kt + BK + 0);
            pa1 = *(const float4*)(aptr + kt + BK + 4);
            pb0 = *(const float4*)(bptr + (size_t)(kt + BK + bkr) * W1_LD + 0);
            pb1 = *(const float4*)(bptr + (size_t)(kt + BK + bkr) * W1_LD + 4);
        }
#pragma unroll
        for (int ks = 0; ks < 2; ks++) {
            int k0 = ks * 8;
            uint32_t ah[4][4], al[4][4];
#pragma unroll
            for (int mi = 0; mi < 4; mi++) {
                int m = wm + mi * 16 + group;
                ah[mi][0] = __float_as_uint(Ah[k0 + tid4][m]);
                ah[mi][1] = __float_as_uint(Ah[k0 + tid4][m + 8]);
                ah[mi][2] = __float_as_uint(Ah[k0 + tid4 + 4][m]);
                ah[mi][3] = __float_as_uint(Ah[k0 + tid4 + 4][m + 8]);
                al[mi][0] = __float_as_uint(Al[k0 + tid4][m]);
                al[mi][1] = __float_as_uint(Al[k0 + tid4][m + 8]);
                al[mi][2] = __float_as_uint(Al[k0 + tid4 + 4][m]);
                al[mi][3] = __float_as_uint(Al[k0 + tid4 + 4][m + 8]);
            }
#pragma unroll
            for (int ni = 0; ni < 4; ni++) {
                int n = wn + ni * 8 + group;
                uint32_t bh0 = __float_as_uint(Bh[k0 + tid4][n]);
                uint32_t bh1 = __float_as_uint(Bh[k0 + tid4 + 4][n]);
                uint32_t bl0 = __float_as_uint(Bl[k0 + tid4][n]);
                uint32_t bl1 = __float_as_uint(Bl[k0 + tid4 + 4][n]);
#pragma unroll
                for (int mi = 0; mi < 4; mi++) {
                    mma_tf32(acc[mi][ni][0], acc[mi][ni][1],
                             acc[mi][ni][2], acc[mi][ni][3],
                             al[mi][0], al[mi][1], al[mi][2], al[mi][3],
                             bh0, bh1);
                    mma_tf32(acc[mi][ni][0], acc[mi][ni][1],
                             acc[mi][ni][2], acc[mi][ni][3],
                             ah[mi][0], ah[mi][1], ah[mi][2], ah[mi][3],
                             bl0, bl1);
                    mma_tf32(acc[mi][ni][0], acc[mi][ni][1],
                             acc[mi][ni][2], acc[mi][ni][3],
                             ah[mi][0], ah[mi][1], ah[mi][2], ah[mi][3],
                             bh0, bh1);
                }
            }
        }
        __syncthreads();
        if (more) {
            float av[8] = {pa0.x, pa0.y, pa0.z, pa0.w, pa1.x, pa1.y, pa1.z, pa1.w};
            float bv[8] = {pb0.x, pb0.y, pb0.z, pb0.w, pb1.x, pb1.y, pb1.z, pb1.w};
#pragma unroll
            for (int q = 0; q < 8; q++) {
                tf32_split(av[q], Ah[akb + q][am], Al[akb + q][am]);
                tf32_split(bv[q], Bh[bkr][bnc + q], Bl[bkr][bnc + q]);
            }
        }
        __syncthreads();
    }

#pragma unroll
    for (int mi = 0; mi < 4; mi++) {
        int rm0 = m0 + wm + mi * 16 + group;
        int rm1 = rm0 + 8;
#pragma unroll
        for (int ni = 0; ni < 4; ni++) {
            int n = n0 + wn + ni * 8 + tid4 * 2;
            if (rm0 < cnt) {
                float2 v = make_float2(gelu_exact(acc[mi][ni][0]),
                                       gelu_exact(acc[mi][ni][1]));
                *(float2*)&g_h[(size_t)(base + rm0) * FF_DIM + n] = v;
            }
            if (rm1 < cnt) {
                float2 v = make_float2(gelu_exact(acc[mi][ni][2]),
                                       gelu_exact(acc[mi][ni][3]));
                *(float2*)&g_h[(size_t)(base + rm1) * FF_DIM + n] = v;
            }
        }
    }
}

// GEMM2: out[tok(row), n] += w(row) * sum_f h[row, f] * w2[(e*FF+f), n]
__global__ __launch_bounds__(256) void gemm2_kernel(
    const float* __restrict__ w2, float* __restrict__ out)
{
    int e = blockIdx.z;
    int base = g_offsets[e];
    int cnt  = g_counts[e];
    int m0   = blockIdx.y * BM;
    if (m0 >= cnt) return;
    int n0   = blockIdx.x * BN;

    __shared__ float Ah[BK][LDS_], Al[BK][LDS_];
    __shared__ float Bh[BK][LDS_], Bl[BK][LDS_];

    int tid  = threadIdx.x;
    int lane = tid & 31;
    int warp = tid >> 5;
    int group = lane >> 2;
    int tid4  = lane & 3;
    int wm = (warp & 1) * 64;
    int wn = (warp >> 1) * 32;

    int am   = tid >> 1;
    int akb  = (tid & 1) * 8;
    int arow = base + m0 + am;
    if (arow >= NSLOT) arow = NSLOT - 1;
    const float* aptr = g_h + (size_t)arow * FF_DIM + akb;

    int bkr = tid >> 4;
    int bnc = (tid & 15) * 8;
    const float* bptr = w2 + (size_t)e * FF_DIM * D_DIM + n0 + bnc;

    float acc[4][4][4];
#pragma unroll
    for (int mi = 0; mi < 4; mi++)
#pragma unroll
        for (int ni = 0; ni < 4; ni++)
#pragma unroll
            for (int c = 0; c < 4; c++) acc[mi][ni][c] = 0.0f;

    float4 pa0 = *(const float4*)(aptr + 0);
    float4 pa1 = *(const float4*)(aptr + 4);
    float4 pb0 = *(const float4*)(bptr + (size_t)bkr * D_DIM + 0);
    float4 pb1 = *(const float4*)(bptr + (size_t)bkr * D_DIM + 4);
    {
        float av[8] = {pa0.x, pa0.y, pa0.z, pa0.w, pa1.x, pa1.y, pa1.z, pa1.w};
        float bv[8] = {pb0.x, pb0.y, pb0.z, pb0.w, pb1.x, pb1.y, pb1.z, pb1.w};
#pragma unroll
        for (int q = 0; q < 8; q++) {
            tf32_split(av[q], Ah[akb + q][am], Al[akb + q][am]);
            tf32_split(bv[q], Bh[bkr][bnc + q], Bl[bkr][bnc + q]);
        }
    }
    __syncthreads();

    for (int kt = 0; kt < FF_DIM; kt += BK) {
        bool more = (kt + BK) < FF_DIM;
        if (more) {
            pa0 = *(const float4*)(aptr + kt + BK + 0);
            pa1 = *(const float4*)(aptr + kt + BK + 4);
            pb0 = *(const float4*)(bptr + (size_t)(kt + BK + bkr) * D_DIM + 0);
            pb1 = *(const float4*)(bptr + (size_t)(kt + BK + bkr) * D_DIM + 4);
        }
#pragma unroll
        for (int ks = 0; ks < 2; ks++) {
            int k0 = ks * 8;
            uint32_t ah[4][4], al[4][4];
#pragma unroll
            for (int mi = 0; mi < 4; mi++) {
                int m = wm + mi * 16 + group;
                ah[mi][0] = __float_as_uint(Ah[k0 + tid4][m]);
                ah[mi][1] = __float_as_uint(Ah[k0 + tid4][m + 8]);
                ah[mi][2] = __float_as_uint(Ah[k0 + tid4 + 4][m]);
                ah[mi][3] = __float_as_uint(Ah[k0 + tid4 + 4][m + 8]);
                al[mi][0] = __float_as_uint(Al[k0 + tid4][m]);
                al[mi][1] = __float_as_uint(Al[k0 + tid4][m + 8]);
                al[mi][2] = __float_as_uint(Al[k0 + tid4 + 4][m]);
                al[mi][3] = __float_as_uint(Al[k0 + tid4 + 4][m + 8]);
            }
#pragma unroll
            for (int ni = 0; ni < 4; ni++) {
                int n = wn + ni * 8 + group;
                uint32_t bh0 = __float_as_uint(Bh[k0 + tid4][n]);
                uint32_t bh1 = __float_as_uint(Bh[k0 + tid4 + 4][n]);
                uint32_t bl0 = __float_as_uint(Bl[k0 + tid4][n]);
                uint32_t bl1 = __float_as_uint(Bl[k0 + tid4 + 4][n]);
#pragma unroll
                for (int mi = 0; mi < 4; mi++) {
                    mma_tf32(acc[mi][ni][0], acc[mi][ni][1],
                             acc[mi][ni][2], acc[mi][ni][3],
                             al[mi][0], al[mi][1], al[mi][2], al[mi][3],
                             bh0, bh1);
                    mma_tf32(acc[mi][ni][0], acc[mi][ni][1],
                             acc[mi][ni][2], acc[mi][ni][3],
                             ah[mi][0], ah[mi][1], ah[mi][2], ah[mi][3],
                             bl0, bl1);
                    mma_tf32(acc[mi][ni][0], acc[mi][ni][1],
                             acc[mi][ni][2], acc[mi][ni][3],
                             ah[mi][0], ah[mi][1], ah[mi][2], ah[mi][3],
                             bh0, bh1);
                }
            }
        }
        __syncthreads();
        if (more) {
            float av[8] = {pa0.x, pa0.y, pa0.z, pa0.w, pa1.x, pa1.y, pa1.z, pa1.w};
            float bv[8] = {pb0.x, pb0.y, pb0.z, pb0.w, pb1.x, pb1.y, pb1.z, pb1.w};
#pragma unroll
            for (int q = 0; q < 8; q++) {
                tf32_split(av[q], Ah[akb + q][am], Al[akb + q][am]);
                tf32_split(bv[q], Bh[bkr][bnc + q], Bl[bkr][bnc + q]);
            }
        }
        __syncthreads();
    }

#pragma unroll
    for (int mi = 0; mi < 4; mi++) {
        int rm0 = m0 + wm + mi * 16 + group;
        int rm1 = rm0 + 8;
        int r0 = base + rm0, r1 = base + rm1;
        int tok0 = 0, tok1 = 0; float w0 = 0.f, w1v = 0.f;
        if (rm0 < cnt) { tok0 = g_slot_token[r0]; w0 = g_slot_w[r0]; }
        if (rm1 < cnt) { tok1 = g_slot_token[r1]; w1v = g_slot_w[r1]; }
#pragma unroll
        for (int ni = 0; ni < 4; ni++) {
            int n = n0 + wn + ni * 8 + tid4 * 2;
            if (rm0 < cnt) {
                float* op = out + (size_t)tok0 * D_DIM + n;
                atomicAdd(op + 0, w0 * acc[mi][ni][0]);
                atomicAdd(op + 1, w0 * acc[mi][ni][1]);
            }
            if (rm1 < cnt) {
                float* op = out + (size_t)tok1 * D_DIM + n;
                atomicAdd(op + 0, w1v * acc[mi][ni][2]);
                atomicAdd(op + 1, w1v * acc[mi][ni][3]);
            }
        }
    }
}

// ---------------- launcher ----------------
extern "C" void kernel_launch(void* const* d_in, const int* in_sizes, int n_in,
                              void* d_out, int out_size) {
    const float* x  = (const float*)d_in[0];
    const float* rw = (const float*)d_in[1];
    const float* w1 = (const float*)d_in[2];
    const float* w2 = (const float*)d_in[3];
    float* out = (float*)d_out;

    zero_out_kernel<<<1024, 256>>>(out, out_size);
    init_kernel<<<1, 64>>>();
    router_kernel<<<T_TOK / 8, 256>>>(x, rw);
    finalize_kernel<<<1, 32>>>(out, out_size);
    scatter_kernel<<<NSLOT / 256, 256>>>();

    dim3 g1(FF_DIM / BN, NSLOT / BM, E_NUM);   // (16, 128, 8)
    gemm1_kernel<<<g1, 256>>>(x, w1);
    dim3 g2(D_DIM / BN, NSLOT / BM, E_NUM);    // (8, 128, 8)
    gemm2_kernel<<<g2, 256>>>(w2, out);
}

// round 4
// speedup vs baseline: 2.2361x; 1.8950x over previous
#include <cuda_runtime.h>
#include <cuda_bf16.h>
#include <math.h>
#include <stdint.h>

// Problem constants
#define T_TOK 8192
#define D_DIM 1024
#define FF_DIM 2048
#define E_NUM 8
#define K_TOP 2
#define NSLOT (T_TOK * K_TOP)
#define W1_LD (E_NUM * FF_DIM)

// ---------------- scratch (device globals; no allocation allowed) ----------
__device__ __nv_bfloat16 g_xh[(size_t)T_TOK * D_DIM];
__device__ __nv_bfloat16 g_xl[(size_t)T_TOK * D_DIM];
__device__ __nv_bfloat16 g_w1h[(size_t)D_DIM * W1_LD];
__device__ __nv_bfloat16 g_w1l[(size_t)D_DIM * W1_LD];
__device__ __nv_bfloat16 g_w2h[(size_t)E_NUM * FF_DIM * D_DIM];
__device__ __nv_bfloat16 g_w2l[(size_t)E_NUM * FF_DIM * D_DIM];
__device__ __nv_bfloat16 g_hh[(size_t)NSLOT * FF_DIM];
__device__ __nv_bfloat16 g_hl[(size_t)NSLOT * FF_DIM];

__device__ int   g_sel[NSLOT];
__device__ float g_wsel[NSLOT];
__device__ int   g_slot_token[NSLOT];
__device__ float g_slot_w[NSLOT];
__device__ int   g_counts[E_NUM];
__device__ int   g_offsets[E_NUM];
__device__ int   g_fill[E_NUM];
__device__ float g_psum[E_NUM];
__device__ float g_zsum;

__device__ __forceinline__ void bf16_split(float v, __nv_bfloat16& h, __nv_bfloat16& l) {
    h = __float2bfloat16_rn(v);
    l = __float2bfloat16_rn(v - __bfloat162float(h));
}

// ---------------- pre-split kernels (f32 -> bf16 hi/lo) --------------------
__global__ void split_x_kernel(const float* __restrict__ src) {
    int n4 = (T_TOK * D_DIM) / 4;
    const float4* s4 = (const float4*)src;
    for (int i = blockIdx.x * blockDim.x + threadIdx.x; i < n4;
         i += gridDim.x * blockDim.x) {
        float4 v = s4[i];
        __nv_bfloat16 h[4], l[4];
        bf16_split(v.x, h[0], l[0]); bf16_split(v.y, h[1], l[1]);
        bf16_split(v.z, h[2], l[2]); bf16_split(v.w, h[3], l[3]);
        ((uint2*)g_xh)[i] = *(uint2*)h;
        ((uint2*)g_xl)[i] = *(uint2*)l;
    }
}
__global__ void split_w1_kernel(const float* __restrict__ src) {
    int n4 = (D_DIM * W1_LD) / 4;
    const float4* s4 = (const float4*)src;
    for (int i = blockIdx.x * blockDim.x + threadIdx.x; i < n4;
         i += gridDim.x * blockDim.x) {
        float4 v = s4[i];
        __nv_bfloat16 h[4], l[4];
        bf16_split(v.x, h[0], l[0]); bf16_split(v.y, h[1], l[1]);
        bf16_split(v.z, h[2], l[2]); bf16_split(v.w, h[3], l[3]);
        ((uint2*)g_w1h)[i] = *(uint2*)h;
        ((uint2*)g_w1l)[i] = *(uint2*)l;
    }
}
__global__ void split_w2_kernel(const float* __restrict__ src) {
    int n4 = (E_NUM * FF_DIM * D_DIM) / 4;
    const float4* s4 = (const float4*)src;
    for (int i = blockIdx.x * blockDim.x + threadIdx.x; i < n4;
         i += gridDim.x * blockDim.x) {
        float4 v = s4[i];
        __nv_bfloat16 h[4], l[4];
        bf16_split(v.x, h[0], l[0]); bf16_split(v.y, h[1], l[1]);
        bf16_split(v.z, h[2], l[2]); bf16_split(v.w, h[3], l[3]);
        ((uint2*)g_w2h)[i] = *(uint2*)h;
        ((uint2*)g_w2l)[i] = *(uint2*)l;
    }
}

// ---------------- kernel 0: zero output ----------------
__global__ void zero_out_kernel(float* out, int n) {
    int idx = blockIdx.x * blockDim.x + threadIdx.x;
    int stride = gridDim.x * blockDim.x;
    for (int i = idx; i < n; i += stride) out[i] = 0.0f;
}

// ---------------- kernel 1: init accumulators ----------------
__global__ void init_kernel() {
    int t = threadIdx.x;
    if (t < E_NUM) {
        g_counts[t] = 0;
        g_fill[t]   = 0;
        g_psum[t]   = 0.0f;
    }
    if (t == 0) g_zsum = 0.0f;
}

// ---------------- kernel 2: router ----------------
__global__ __launch_bounds__(256) void router_kernel(
    const float* __restrict__ x, const float* __restrict__ rw)
{
    __shared__ float s_rw[E_NUM * D_DIM];
    __shared__ float sp[E_NUM];
    __shared__ int   sc[E_NUM];
    __shared__ float sz;

    int tid = threadIdx.x;
    for (int i = tid; i < E_NUM * D_DIM; i += 256) s_rw[i] = rw[i];
    if (tid < E_NUM) { sp[tid] = 0.0f; sc[tid] = 0; }
    if (tid == 0) sz = 0.0f;
    __syncthreads();

    int warp = tid >> 5;
    int lane = tid & 31;
    int t = blockIdx.x * 8 + warp;

    float acc[E_NUM];
#pragma unroll
    for (int e = 0; e < E_NUM; e++) acc[e] = 0.0f;

    const float* xr = x + (size_t)t * D_DIM;
    for (int d = lane; d < D_DIM; d += 32) {
        float xv = xr[d];
#pragma unroll
        for (int e = 0; e < E_NUM; e++) acc[e] += xv * s_rw[e * D_DIM + d];
    }
#pragma unroll
    for (int e = 0; e < E_NUM; e++) {
#pragma unroll
        for (int off = 16; off > 0; off >>= 1)
            acc[e] += __shfl_xor_sync(0xFFFFFFFF, acc[e], off);
    }

    if (lane == 0) {
        float m = acc[0];
#pragma unroll
        for (int e = 1; e < E_NUM; e++) m = fmaxf(m, acc[e]);
        float p[E_NUM], s = 0.0f;
#pragma unroll
        for (int e = 0; e < E_NUM; e++) { p[e] = expf(acc[e] - m); s += p[e]; }
        float inv = 1.0f / s;
        float lse = m + logf(s);

        int i1 = 0;
#pragma unroll
        for (int e = 1; e < E_NUM; e++) if (acc[e] > acc[i1]) i1 = e;
        int i2 = (i1 == 0) ? 1 : 0;
#pragma unroll
        for (int e = 0; e < E_NUM; e++)
            if (e != i1 && acc[e] > acc[i2]) i2 = e;

        float p1 = p[i1] * inv, p2 = p[i2] * inv;
        float winv = 1.0f / (p1 + p2);
        g_sel[2 * t]      = i1;
        g_wsel[2 * t]     = p1 * winv;
        g_sel[2 * t + 1]  = i2;
        g_wsel[2 * t + 1] = p2 * winv;

#pragma unroll
        for (int e = 0; e < E_NUM; e++) atomicAdd(&sp[e], p[e] * inv);
        atomicAdd(&sz, lse * lse);
        atomicAdd(&sc[i1], 1);
        atomicAdd(&sc[i2], 1);
    }
    __syncthreads();
    if (tid < E_NUM) {
        atomicAdd(&g_psum[tid], sp[tid]);
        atomicAdd(&g_counts[tid], sc[tid]);
    }
    if (tid == 0) atomicAdd(&g_zsum, sz);
}

// ---------------- kernel 3: finalize losses + offsets scan ----------------
__global__ void finalize_kernel(float* out, int out_size) {
    if (threadIdx.x == 0 && blockIdx.x == 0) {
        int off = 0;
        for (int e = 0; e < E_NUM; e++) { g_offsets[e] = off; off += g_counts[e]; }
        float z = g_zsum / (float)T_TOK;
        float lb = 0.0f;
        for (int e = 0; e < E_NUM; e++)
            lb += ((float)g_counts[e] / (float)(T_TOK * K_TOP)) *
                  (g_psum[e] / (float)T_TOK);
        lb *= (float)E_NUM;
        out[out_size - 2] = z;
        out[out_size - 1] = lb;
    }
}

// ---------------- kernel 4: scatter into expert groups ----------------
__global__ void scatter_kernel() {
    int s = blockIdx.x * blockDim.x + threadIdx.x;
    if (s >= NSLOT) return;
    int e = g_sel[s];
    int pos = g_offsets[e] + atomicAdd(&g_fill[e], 1);
    g_slot_token[pos] = s >> 1;
    g_slot_w[pos]     = g_wsel[s];
}

// ============== bf16x3 tensor-core grouped GEMMs ===========================
// Tile BM=128, BN=128, BK=32 (bf16). 256 thr = 8 warps (2M x 4N), warp 64x32.
// mma.m16n8k16.bf16: acc = ah*bh + ah*bl + al*bh (hi/lo pre-split in gmem).
// A smem [m][k] (ldmatrix x4), B smem [k][n] (ldmatrix x4 trans).
#define BM 128
#define BN 128
#define BKB 32
#define AKP 40    // A row stride (bf16): 80 B -> bank perm 20m mod 32
#define BNP 136   // B row stride (bf16): 272 B -> bank perm 4k mod 32

__device__ __forceinline__ float gelu_exact(float v) {
    return 0.5f * v * (1.0f + erff(v * 0.70710678118654752f));
}

__device__ __forceinline__ void mma_bf16(
    float& c0, float& c1, float& c2, float& c3,
    uint32_t a0, uint32_t a1, uint32_t a2, uint32_t a3,
    uint32_t b0, uint32_t b1)
{
    asm volatile(
        "mma.sync.aligned.m16n8k16.row.col.f32.bf16.bf16.f32 "
        "{%0,%1,%2,%3}, {%4,%5,%6,%7}, {%8,%9}, {%0,%1,%2,%3};"
        : "+f"(c0), "+f"(c1), "+f"(c2), "+f"(c3)
        : "r"(a0), "r"(a1), "r"(a2), "r"(a3), "r"(b0), "r"(b1));
}

__device__ __forceinline__ void ldsm_x4(uint32_t* r, const void* p) {
    uint32_t addr = (uint32_t)__cvta_generic_to_shared(p);
    asm volatile("ldmatrix.sync.aligned.m8n8.x4.shared.b16 {%0,%1,%2,%3}, [%4];"
                 : "=r"(r[0]), "=r"(r[1]), "=r"(r[2]), "=r"(r[3]) : "r"(addr));
}
__device__ __forceinline__ void ldsm_x4_trans(uint32_t* r, const void* p) {
    uint32_t addr = (uint32_t)__cvta_generic_to_shared(p);
    asm volatile("ldmatrix.sync.aligned.m8n8.x4.trans.shared.b16 {%0,%1,%2,%3}, [%4];"
                 : "=r"(r[0]), "=r"(r[1]), "=r"(r[2]), "=r"(r[3]) : "r"(addr));
}

// GEMM1: h = gelu( x_gathered @ w1_e )   [slots x FF]
__global__ __launch_bounds__(256) void gemm1_kernel() {
    int e = blockIdx.z;
    int base = g_offsets[e];
    int cnt  = g_counts[e];
    int m0   = blockIdx.y * BM;
    if (m0 >= cnt) return;
    int n0   = blockIdx.x * BN;

    __shared__ __nv_bfloat16 Ah[BM][AKP], Al[BM][AKP];
    __shared__ __nv_bfloat16 Bh[BKB][BNP], Bl[BKB][BNP];

    int tid  = threadIdx.x;
    int lane = tid & 31;
    int warp = tid >> 5;
    int group = lane >> 2;
    int tid4  = lane & 3;
    int wm = (warp & 1) * 64;
    int wn = (warp >> 1) * 32;
    int lrow = lane & 15;
    int lcol = (lane >> 4) << 3;

    int am = tid >> 1;
    int kb = (tid & 1) * 16;
    int arow = base + m0 + am;
    int tok  = g_slot_token[arow < NSLOT ? arow : NSLOT - 1];
    const __nv_bfloat16* aph = g_xh + (size_t)tok * D_DIM + kb;
    const __nv_bfloat16* apl = g_xl + (size_t)tok * D_DIM + kb;

    int bkr = tid >> 3;
    int bnc = (tid & 7) * 16;
    size_t bbase = (size_t)e * FF_DIM + n0 + bnc;

    float acc[4][4][4];
#pragma unroll
    for (int mi = 0; mi < 4; mi++)
#pragma unroll
        for (int ni = 0; ni < 4; ni++)
#pragma unroll
            for (int c = 0; c < 4; c++) acc[mi][ni][c] = 0.0f;

    uint4 pah0 = *(const uint4*)(aph + 0);
    uint4 pah1 = *(const uint4*)(aph + 8);
    uint4 pal0 = *(const uint4*)(apl + 0);
    uint4 pal1 = *(const uint4*)(apl + 8);
    uint4 pbh0 = *(const uint4*)(g_w1h + (size_t)bkr * W1_LD + bbase);
    uint4 pbh1 = *(const uint4*)(g_w1h + (size_t)bkr * W1_LD + bbase + 8);
    uint4 pbl0 = *(const uint4*)(g_w1l + (size_t)bkr * W1_LD + bbase);
    uint4 pbl1 = *(const uint4*)(g_w1l + (size_t)bkr * W1_LD + bbase + 8);
    *(uint4*)&Ah[am][kb]     = pah0; *(uint4*)&Ah[am][kb + 8]  = pah1;
    *(uint4*)&Al[am][kb]     = pal0; *(uint4*)&Al[am][kb + 8]  = pal1;
    *(uint4*)&Bh[bkr][bnc]   = pbh0; *(uint4*)&Bh[bkr][bnc + 8] = pbh1;
    *(uint4*)&Bl[bkr][bnc]   = pbl0; *(uint4*)&Bl[bkr][bnc + 8] = pbl1;
    __syncthreads();

    for (int kt = 0; kt < D_DIM; kt += BKB) {
        bool more = (kt + BKB) < D_DIM;
        if (more) {
            pah0 = *(const uint4*)(aph + kt + BKB + 0);
            pah1 = *(const uint4*)(aph + kt + BKB + 8);
            pal0 = *(const uint4*)(apl + kt + BKB + 0);
            pal1 = *(const uint4*)(apl + kt + BKB + 8);
            pbh0 = *(const uint4*)(g_w1h + (size_t)(kt + BKB + bkr) * W1_LD + bbase);
            pbh1 = *(const uint4*)(g_w1h + (size_t)(kt + BKB + bkr) * W1_LD + bbase + 8);
            pbl0 = *(const uint4*)(g_w1l + (size_t)(kt + BKB + bkr) * W1_LD + bbase);
            pbl1 = *(const uint4*)(g_w1l + (size_t)(kt + BKB + bkr) * W1_LD + bbase + 8);
        }
#pragma unroll
        for (int ks = 0; ks < 2; ks++) {
            int k0 = ks * 16;
            uint32_t ah[4][4], al[4][4], bh[4][2], bl[4][2];
#pragma unroll
            for (int mi = 0; mi < 4; mi++) {
                ldsm_x4(ah[mi], &Ah[wm + mi * 16 + lrow][k0 + lcol]);
                ldsm_x4(al[mi], &Al[wm + mi * 16 + lrow][k0 + lcol]);
            }
#pragma unroll
            for (int nh = 0; nh < 2; nh++) {
                uint32_t r[4];
                ldsm_x4_trans(r, &Bh[k0 + lrow][wn + nh * 16 + lcol]);
                bh[2 * nh][0] = r[0]; bh[2 * nh][1] = r[1];
                bh[2 * nh + 1][0] = r[2]; bh[2 * nh + 1][1] = r[3];
                ldsm_x4_trans(r, &Bl[k0 + lrow][wn + nh * 16 + lcol]);
                bl[2 * nh][0] = r[0]; bl[2 * nh][1] = r[1];
                bl[2 * nh + 1][0] = r[2]; bl[2 * nh + 1][1] = r[3];
            }
#pragma unroll
            for (int mi = 0; mi < 4; mi++)
#pragma unroll
                for (int ni = 0; ni < 4; ni++) {
                    mma_bf16(acc[mi][ni][0], acc[mi][ni][1], acc[mi][ni][2], acc[mi][ni][3],
                             al[mi][0], al[mi][1], al[mi][2], al[mi][3],
                             bh[ni][0], bh[ni][1]);
                    mma_bf16(acc[mi][ni][0], acc[mi][ni][1], acc[mi][ni][2], acc[mi][ni][3],
                             ah[mi][0], ah[mi][1], ah[mi][2], ah[mi][3],
                             bl[ni][0], bl[ni][1]);
                    mma_bf16(acc[mi][ni][0], acc[mi][ni][1], acc[mi][ni][2], acc[mi][ni][3],
                             ah[mi][0], ah[mi][1], ah[mi][2], ah[mi][3],
                             bh[ni][0], bh[ni][1]);
                }
        }
        __syncthreads();
        if (more) {
            *(uint4*)&Ah[am][kb]      = pah0; *(uint4*)&Ah[am][kb + 8]   = pah1;
            *(uint4*)&Al[am][kb]      = pal0; *(uint4*)&Al[am][kb + 8]   = pal1;
            *(uint4*)&Bh[bkr][bnc]    = pbh0; *(uint4*)&Bh[bkr][bnc + 8] = pbh1;
            *(uint4*)&Bl[bkr][bnc]    = pbl0; *(uint4*)&Bl[bkr][bnc + 8] = pbl1;
        }
        __syncthreads();
    }

    // epilogue: gelu -> split -> g_hh/g_hl
#pragma unroll
    for (int mi = 0; mi < 4; mi++) {
        int rm0 = m0 + wm + mi * 16 + group;
        int rm1 = rm0 + 8;
#pragma unroll
        for (int ni = 0; ni < 4; ni++) {
            int n = n0 + wn + ni * 8 + tid4 * 2;
            if (rm0 < cnt) {
                float v0 = gelu_exact(acc[mi][ni][0]);
                float v1 = gelu_exact(acc[mi][ni][1]);
                __nv_bfloat16 h0, l0, h1, l1;
                bf16_split(v0, h0, l0); bf16_split(v1, h1, l1);
                size_t o = (size_t)(base + rm0) * FF_DIM + n;
                *(__nv_bfloat162*)(g_hh + o) = __halves2bfloat162(h0, h1);
                *(__nv_bfloat162*)(g_hl + o) = __halves2bfloat162(l0, l1);
            }
            if (rm1 < cnt) {
                float v0 = gelu_exact(acc[mi][ni][2]);
                float v1 = gelu_exact(acc[mi][ni][3]);
                __nv_bfloat16 h0, l0, h1, l1;
                bf16_split(v0, h0, l0); bf16_split(v1, h1, l1);
                size_t o = (size_t)(base + rm1) * FF_DIM + n;
                *(__nv_bfloat162*)(g_hh + o) = __halves2bfloat162(h0, h1);
                *(__nv_bfloat162*)(g_hl + o) = __halves2bfloat162(l0, l1);
            }
        }
    }
}

// GEMM2: out[tok(row)] += w(row) * ( h[row] @ w2_e )
__global__ __launch_bounds__(256) void gemm2_kernel(float* __restrict__ out) {
    int e = blockIdx.z;
    int base = g_offsets[e];
    int cnt  = g_counts[e];
    int m0   = blockIdx.y * BM;
    if (m0 >= cnt) return;
    int n0   = blockIdx.x * BN;

    __shared__ __nv_bfloat16 Ah[BM][AKP], Al[BM][AKP];
    __shared__ __nv_bfloat16 Bh[BKB][BNP], Bl[BKB][BNP];

    int tid  = threadIdx.x;
    int lane = tid & 31;
    int warp = tid >> 5;
    int group = lane >> 2;
    int tid4  = lane & 3;
    int wm = (warp & 1) * 64;
    int wn = (warp >> 1) * 32;
    int lrow = lane & 15;
    int lcol = (lane >> 4) << 3;

    int am = tid >> 1;
    int kb = (tid & 1) * 16;
    int arow = base + m0 + am;
    if (arow >= NSLOT) arow = NSLOT - 1;
    const __nv_bfloat16* aph = g_hh + (size_t)arow * FF_DIM + kb;
    const __nv_bfloat16* apl = g_hl + (size_t)arow * FF_DIM + kb;

    int bkr = tid >> 3;
    int bnc = (tid & 7) * 16;
    size_t bbase = (size_t)e * FF_DIM * D_DIM + n0 + bnc;

    float acc[4][4][4];
#pragma unroll
    for (int mi = 0; mi < 4; mi++)
#pragma unroll
        for (int ni = 0; ni < 4; ni++)
#pragma unroll
            for (int c = 0; c < 4; c++) acc[mi][ni][c] = 0.0f;

    uint4 pah0 = *(const uint4*)(aph + 0);
    uint4 pah1 = *(const uint4*)(aph + 8);
    uint4 pal0 = *(const uint4*)(apl + 0);
    uint4 pal1 = *(const uint4*)(apl + 8);
    uint4 pbh0 = *(const uint4*)(g_w2h + (size_t)bkr * D_DIM + bbase);
    uint4 pbh1 = *(const uint4*)(g_w2h + (size_t)bkr * D_DIM + bbase + 8);
    uint4 pbl0 = *(const uint4*)(g_w2l + (size_t)bkr * D_DIM + bbase);
    uint4 pbl1 = *(const uint4*)(g_w2l + (size_t)bkr * D_DIM + bbase + 8);
    *(uint4*)&Ah[am][kb]     = pah0; *(uint4*)&Ah[am][kb + 8]  = pah1;
    *(uint4*)&Al[am][kb]     = pal0; *(uint4*)&Al[am][kb + 8]  = pal1;
    *(uint4*)&Bh[bkr][bnc]   = pbh0; *(uint4*)&Bh[bkr][bnc + 8] = pbh1;
    *(uint4*)&Bl[bkr][bnc]   = pbl0; *(uint4*)&Bl[bkr][bnc + 8] = pbl1;
    __syncthreads();

    for (int kt = 0; kt < FF_DIM; kt += BKB) {
        bool more = (kt + BKB) < FF_DIM;
        if (more) {
            pah0 = *(const uint4*)(aph + kt + BKB + 0);
            pah1 = *(const uint4*)(aph + kt + BKB + 8);
            pal0 = *(const uint4*)(apl + kt + BKB + 0);
            pal1 = *(const uint4*)(apl + kt + BKB + 8);
            pbh0 = *(const uint4*)(g_w2h + (size_t)(kt + BKB + bkr) * D_DIM + bbase);
            pbh1 = *(const uint4*)(g_w2h + (size_t)(kt + BKB + bkr) * D_DIM + bbase + 8);
            pbl0 = *(const uint4*)(g_w2l + (size_t)(kt + BKB + bkr) * D_DIM + bbase);
            pbl1 = *(const uint4*)(g_w2l + (size_t)(kt + BKB + bkr) * D_DIM + bbase + 8);
        }
#pragma unroll
        for (int ks = 0; ks < 2; ks++) {
            int k0 = ks * 16;
            uint32_t ah[4][4], al[4][4], bh[4][2], bl[4][2];
#pragma unroll
            for (int mi = 0; mi < 4; mi++) {
                ldsm_x4(ah[mi], &Ah[wm + mi * 16 + lrow][k0 + lcol]);
                ldsm_x4(al[mi], &Al[wm + mi * 16 + lrow][k0 + lcol]);
            }
#pragma unroll
            for (int nh = 0; nh < 2; nh++) {
                uint32_t r[4];
                ldsm_x4_trans(r, &Bh[k0 + lrow][wn + nh * 16 + lcol]);
                bh[2 * nh][0] = r[0]; bh[2 * nh][1] = r[1];
                bh[2 * nh + 1][0] = r[2]; bh[2 * nh + 1][1] = r[3];
                ldsm_x4_trans(r, &Bl[k0 + lrow][wn + nh * 16 + lcol]);
                bl[2 * nh][0] = r[0]; bl[2 * nh][1] = r[1];
                bl[2 * nh + 1][0] = r[2]; bl[2 * nh + 1][1] = r[3];
            }
#pragma unroll
            for (int mi = 0; mi < 4; mi++)
#pragma unroll
                for (int ni = 0; ni < 4; ni++) {
                    mma_bf16(acc[mi][ni][0], acc[mi][ni][1], acc[mi][ni][2], acc[mi][ni][3],
                             al[mi][0], al[mi][1], al[mi][2], al[mi][3],
                             bh[ni][0], bh[ni][1]);
                    mma_bf16(acc[mi][ni][0], acc[mi][ni][1], acc[mi][ni][2], acc[mi][ni][3],
                             ah[mi][0], ah[mi][1], ah[mi][2], ah[mi][3],
                             bl[ni][0], bl[ni][1]);
                    mma_bf16(acc[mi][ni][0], acc[mi][ni][1], acc[mi][ni][2], acc[mi][ni][3],
                             ah[mi][0], ah[mi][1], ah[mi][2], ah[mi][3],
                             bh[ni][0], bh[ni][1]);
                }
        }
        __syncthreads();
        if (more) {
            *(uint4*)&Ah[am][kb]      = pah0; *(uint4*)&Ah[am][kb + 8]   = pah1;
            *(uint4*)&Al[am][kb]      = pal0; *(uint4*)&Al[am][kb + 8]   = pal1;
            *(uint4*)&Bh[bkr][bnc]    = pbh0; *(uint4*)&Bh[bkr][bnc + 8] = pbh1;
            *(uint4*)&Bl[bkr][bnc]    = pbl0; *(uint4*)&Bl[bkr][bnc + 8] = pbl1;
        }
        __syncthreads();
    }

    // epilogue: weighted atomic scatter
#pragma unroll
    for (int mi = 0; mi < 4; mi++) {
        int rm0 = m0 + wm + mi * 16 + group;
        int rm1 = rm0 + 8;
        int r0 = base + rm0, r1 = base + rm1;
        int tok0 = 0, tok1 = 0; float w0 = 0.f, w1v = 0.f;
        if (rm0 < cnt) { tok0 = g_slot_token[r0]; w0 = g_slot_w[r0]; }
        if (rm1 < cnt) { tok1 = g_slot_token[r1]; w1v = g_slot_w[r1]; }
#pragma unroll
        for (int ni = 0; ni < 4; ni++) {
            int n = n0 + wn + ni * 8 + tid4 * 2;
            if (rm0 < cnt) {
                float* op = out + (size_t)tok0 * D_DIM + n;
                atomicAdd(op + 0, w0 * acc[mi][ni][0]);
                atomicAdd(op + 1, w0 * acc[mi][ni][1]);
            }
            if (rm1 < cnt) {
                float* op = out + (size_t)tok1 * D_DIM + n;
                atomicAdd(op + 0, w1v * acc[mi][ni][2]);
                atomicAdd(op + 1, w1v * acc[mi][ni][3]);
            }
        }
    }
}

// ---------------- launcher ----------------
extern "C" void kernel_launch(void* const* d_in, const int* in_sizes, int n_in,
                              void* d_out, int out_size) {
    const float* x  = (const float*)d_in[0];
    const float* rw = (const float*)d_in[1];
    const float* w1 = (const float*)d_in[2];
    const float* w2 = (const float*)d_in[3];
    float* out = (float*)d_out;

    zero_out_kernel<<<1024, 256>>>(out, out_size);
    init_kernel<<<1, 64>>>();
    split_x_kernel<<<2048, 256>>>(x);
    split_w1_kernel<<<4096, 256>>>(w1);
    split_w2_kernel<<<4096, 256>>>(w2);
    router_kernel<<<T_TOK / 8, 256>>>(x, rw);
    finalize_kernel<<<1, 32>>>(out, out_size);
    scatter_kernel<<<NSLOT / 256, 256>>>();

    dim3 g1(FF_DIM / BN, NSLOT / BM, E_NUM);
    gemm1_kernel<<<g1, 256>>>();
    dim3 g2(D_DIM / BN, NSLOT / BM, E_NUM);
    gemm2_kernel<<<g2, 256>>>(out);
}

// round 9
// speedup vs baseline: 3.3595x; 1.5024x over previous
#include <cuda_runtime.h>
#include <cuda_fp16.h>
#include <math.h>
#include <stdint.h>

// Problem constants
#define T_TOK 8192
#define D_DIM 1024
#define FF_DIM 2048
#define E_NUM 8
#define K_TOP 2
#define NSLOT (T_TOK * K_TOP)
#define W1_LD (E_NUM * FF_DIM)

// ---------------- scratch (device globals) ---------------------------------
__device__ __half g_xh[(size_t)T_TOK * D_DIM];
__device__ __half g_xl[(size_t)T_TOK * D_DIM];
__device__ __half g_w1h[(size_t)D_DIM * W1_LD];
__device__ __half g_w2h[(size_t)E_NUM * FF_DIM * D_DIM];
__device__ __half g_hh[(size_t)NSLOT * FF_DIM];
__device__ __half g_hl[(size_t)NSLOT * FF_DIM];

__device__ int   g_sel[NSLOT];
__device__ float g_wsel[NSLOT];
__device__ int   g_slot_token[NSLOT];
__device__ float g_slot_w[NSLOT];
__device__ int   g_counts[E_NUM];
__device__ int   g_offsets[E_NUM];
__device__ int   g_fill[E_NUM];
__device__ float g_psum[E_NUM];
__device__ float g_zsum;

__device__ __forceinline__ void f16_split(float v, __half& h, __half& l) {
    h = __float2half_rn(v);
    l = __float2half_rn(v - __half2float(h));
}

// ---------------- pre-split / convert kernels ------------------------------
__global__ void split_x_kernel(const float* __restrict__ src) {
    int n4 = (T_TOK * D_DIM) / 4;
    const float4* s4 = (const float4*)src;
    for (int i = blockIdx.x * blockDim.x + threadIdx.x; i < n4;
         i += gridDim.x * blockDim.x) {
        float4 v = s4[i];
        __half h[4], l[4];
        f16_split(v.x, h[0], l[0]); f16_split(v.y, h[1], l[1]);
        f16_split(v.z, h[2], l[2]); f16_split(v.w, h[3], l[3]);
        ((uint2*)g_xh)[i] = *(uint2*)h;
        ((uint2*)g_xl)[i] = *(uint2*)l;
    }
}
__global__ void cvt_w1_kernel(const float* __restrict__ src) {
    int n4 = (D_DIM * W1_LD) / 4;
    const float4* s4 = (const float4*)src;
    for (int i = blockIdx.x * blockDim.x + threadIdx.x; i < n4;
         i += gridDim.x * blockDim.x) {
        float4 v = s4[i];
        __half h[4];
        h[0] = __float2half_rn(v.x); h[1] = __float2half_rn(v.y);
        h[2] = __float2half_rn(v.z); h[3] = __float2half_rn(v.w);
        ((uint2*)g_w1h)[i] = *(uint2*)h;
    }
}
__global__ void cvt_w2_kernel(const float* __restrict__ src) {
    int n4 = (E_NUM * FF_DIM * D_DIM) / 4;
    const float4* s4 = (const float4*)src;
    for (int i = blockIdx.x * blockDim.x + threadIdx.x; i < n4;
         i += gridDim.x * blockDim.x) {
        float4 v = s4[i];
        __half h[4];
        h[0] = __float2half_rn(v.x); h[1] = __float2half_rn(v.y);
        h[2] = __float2half_rn(v.z); h[3] = __float2half_rn(v.w);
        ((uint2*)g_w2h)[i] = *(uint2*)h;
    }
}

// ---------------- kernel 0: zero output ----------------
__global__ void zero_out_kernel(float* out, int n) {
    int idx = blockIdx.x * blockDim.x + threadIdx.x;
    int stride = gridDim.x * blockDim.x;
    for (int i = idx; i < n; i += stride) out[i] = 0.0f;
}

// ---------------- kernel 1: init accumulators ----------------
__global__ void init_kernel() {
    int t = threadIdx.x;
    if (t < E_NUM) { g_counts[t] = 0; g_fill[t] = 0; g_psum[t] = 0.0f; }
    if (t == 0) g_zsum = 0.0f;
}

// ---------------- kernel 2: router ----------------
__global__ __launch_bounds__(256) void router_kernel(
    const float* __restrict__ x, const float* __restrict__ rw)
{
    __shared__ float s_rw[E_NUM * D_DIM];
    __shared__ float sp[E_NUM];
    __shared__ int   sc[E_NUM];
    __shared__ float sz;

    int tid = threadIdx.x;
    for (int i = tid; i < E_NUM * D_DIM; i += 256) s_rw[i] = rw[i];
    if (tid < E_NUM) { sp[tid] = 0.0f; sc[tid] = 0; }
    if (tid == 0) sz = 0.0f;
    __syncthreads();

    int warp = tid >> 5;
    int lane = tid & 31;
    int t = blockIdx.x * 8 + warp;

    float acc[E_NUM];
#pragma unroll
    for (int e = 0; e < E_NUM; e++) acc[e] = 0.0f;

    const float* xr = x + (size_t)t * D_DIM;
    for (int d = lane; d < D_DIM; d += 32) {
        float xv = xr[d];
#pragma unroll
        for (int e = 0; e < E_NUM; e++) acc[e] += xv * s_rw[e * D_DIM + d];
    }
#pragma unroll
    for (int e = 0; e < E_NUM; e++) {
#pragma unroll
        for (int off = 16; off > 0; off >>= 1)
            acc[e] += __shfl_xor_sync(0xFFFFFFFF, acc[e], off);
    }

    if (lane == 0) {
        float m = acc[0];
#pragma unroll
        for (int e = 1; e < E_NUM; e++) m = fmaxf(m, acc[e]);
        float p[E_NUM], s = 0.0f;
#pragma unroll
        for (int e = 0; e < E_NUM; e++) { p[e] = expf(acc[e] - m); s += p[e]; }
        float inv = 1.0f / s;
        float lse = m + logf(s);

        int i1 = 0;
#pragma unroll
        for (int e = 1; e < E_NUM; e++) if (acc[e] > acc[i1]) i1 = e;
        int i2 = (i1 == 0) ? 1 : 0;
#pragma unroll
        for (int e = 0; e < E_NUM; e++)
            if (e != i1 && acc[e] > acc[i2]) i2 = e;

        float p1 = p[i1] * inv, p2 = p[i2] * inv;
        float winv = 1.0f / (p1 + p2);
        g_sel[2 * t]      = i1;
        g_wsel[2 * t]     = p1 * winv;
        g_sel[2 * t + 1]  = i2;
        g_wsel[2 * t + 1] = p2 * winv;

#pragma unroll
        for (int e = 0; e < E_NUM; e++) atomicAdd(&sp[e], p[e] * inv);
        atomicAdd(&sz, lse * lse);
        atomicAdd(&sc[i1], 1);
        atomicAdd(&sc[i2], 1);
    }
    __syncthreads();
    if (tid < E_NUM) {
        atomicAdd(&g_psum[tid], sp[tid]);
        atomicAdd(&g_counts[tid], sc[tid]);
    }
    if (tid == 0) atomicAdd(&g_zsum, sz);
}

// ---------------- kernel 3: finalize losses + offsets scan ----------------
__global__ void finalize_kernel(float* out, int out_size) {
    if (threadIdx.x == 0 && blockIdx.x == 0) {
        int off = 0;
        for (int e = 0; e < E_NUM; e++) { g_offsets[e] = off; off += g_counts[e]; }
        float z = g_zsum / (float)T_TOK;
        float lb = 0.0f;
        for (int e = 0; e < E_NUM; e++)
            lb += ((float)g_counts[e] / (float)(T_TOK * K_TOP)) *
                  (g_psum[e] / (float)T_TOK);
        lb *= (float)E_NUM;
        out[out_size - 2] = z;
        out[out_size - 1] = lb;
    }
}

// ---------------- kernel 4: scatter into expert groups ----------------
__global__ void scatter_kernel() {
    int s = blockIdx.x * blockDim.x + threadIdx.x;
    if (s >= NSLOT) return;
    int e = g_sel[s];
    int pos = g_offsets[e] + atomicAdd(&g_fill[e], 1);
    g_slot_token[pos] = s >> 1;
    g_slot_w[pos]     = g_wsel[s];
}

// ============== fp16 2-limb tensor-core grouped GEMMs ======================
// Tile BM=128, BN=128, BK=32. 256 thr = 8 warps (2M x 4N), warp 64x32.
// mma.m16n8k16.f16: acc = ah*bh + al*bh (A = activations, 2 limbs; B = weights, 1 limb).
#define BM 128
#define BN 128
#define BKB 32
#define AKP 40    // A row stride (half): 80 B
#define BNP 136   // B row stride (half): 272 B

__device__ __forceinline__ float gelu_exact(float v) {
    return 0.5f * v * (1.0f + erff(v * 0.70710678118654752f));
}

__device__ __forceinline__ void mma_f16(
    float& c0, float& c1, float& c2, float& c3,
    uint32_t a0, uint32_t a1, uint32_t a2, uint32_t a3,
    uint32_t b0, uint32_t b1)
{
    asm volatile(
        "mma.sync.aligned.m16n8k16.row.col.f32.f16.f16.f32 "
        "{%0,%1,%2,%3}, {%4,%5,%6,%7}, {%8,%9}, {%0,%1,%2,%3};"
        : "+f"(c0), "+f"(c1), "+f"(c2), "+f"(c3)
        : "r"(a0), "r"(a1), "r"(a2), "r"(a3), "r"(b0), "r"(b1));
}

__device__ __forceinline__ void ldsm_x4(uint32_t* r, const void* p) {
    uint32_t addr = (uint32_t)__cvta_generic_to_shared(p);
    asm volatile("ldmatrix.sync.aligned.m8n8.x4.shared.b16 {%0,%1,%2,%3}, [%4];"
                 : "=r"(r[0]), "=r"(r[1]), "=r"(r[2]), "=r"(r[3]) : "r"(addr));
}
__device__ __forceinline__ void ldsm_x4_trans(uint32_t* r, const void* p) {
    uint32_t addr = (uint32_t)__cvta_generic_to_shared(p);
    asm volatile("ldmatrix.sync.aligned.m8n8.x4.trans.shared.b16 {%0,%1,%2,%3}, [%4];"
                 : "=r"(r[0]), "=r"(r[1]), "=r"(r[2]), "=r"(r[3]) : "r"(addr));
}

// GEMM1: h = gelu( x_gathered @ w1_e )   [slots x FF]
__global__ __launch_bounds__(256) void gemm1_kernel() {
    int e = blockIdx.z;
    int base = g_offsets[e];
    int cnt  = g_counts[e];
    int m0   = blockIdx.y * BM;
    if (m0 >= cnt) return;
    int n0   = blockIdx.x * BN;

    __shared__ __half Ah[BM][AKP], Al[BM][AKP];
    __shared__ __half Bh[BKB][BNP];

    int tid  = threadIdx.x;
    int lane = tid & 31;
    int warp = tid >> 5;
    int group = lane >> 2;
    int tid4  = lane & 3;
    int wm = (warp & 1) * 64;
    int wn = (warp >> 1) * 32;
    int lrow = lane & 15;
    int lcol = (lane >> 4) << 3;

    int am = tid >> 1;
    int kb = (tid & 1) * 16;
    int arow = base + m0 + am;
    int tok  = g_slot_token[arow < NSLOT ? arow : NSLOT - 1];
    const __half* aph = g_xh + (size_t)tok * D_DIM + kb;
    const __half* apl = g_xl + (size_t)tok * D_DIM + kb;

    int bkr = tid >> 3;
    int bnc = (tid & 7) * 16;
    size_t bbase = (size_t)e * FF_DIM + n0 + bnc;

    float acc[4][4][4];
#pragma unroll
    for (int mi = 0; mi < 4; mi++)
#pragma unroll
        for (int ni = 0; ni < 4; ni++)
#pragma unroll
            for (int c = 0; c < 4; c++) acc[mi][ni][c] = 0.0f;

    uint4 pah0 = *(const uint4*)(aph + 0);
    uint4 pah1 = *(const uint4*)(aph + 8);
    uint4 pal0 = *(const uint4*)(apl + 0);
    uint4 pal1 = *(const uint4*)(apl + 8);
    uint4 pbh0 = *(const uint4*)(g_w1h + (size_t)bkr * W1_LD + bbase);
    uint4 pbh1 = *(const uint4*)(g_w1h + (size_t)bkr * W1_LD + bbase + 8);
    *(uint4*)&Ah[am][kb]     = pah0; *(uint4*)&Ah[am][kb + 8]   = pah1;
    *(uint4*)&Al[am][kb]     = pal0; *(uint4*)&Al[am][kb + 8]   = pal1;
    *(uint4*)&Bh[bkr][bnc]   = pbh0; *(uint4*)&Bh[bkr][bnc + 8] = pbh1;
    __syncthreads();

    for (int kt = 0; kt < D_DIM; kt += BKB) {
        bool more = (kt + BKB) < D_DIM;
        if (more) {
            pah0 = *(const uint4*)(aph + kt + BKB + 0);
            pah1 = *(const uint4*)(aph + kt + BKB + 8);
            pal0 = *(const uint4*)(apl + kt + BKB + 0);
            pal1 = *(const uint4*)(apl + kt + BKB + 8);
            pbh0 = *(const uint4*)(g_w1h + (size_t)(kt + BKB + bkr) * W1_LD + bbase);
            pbh1 = *(const uint4*)(g_w1h + (size_t)(kt + BKB + bkr) * W1_LD + bbase + 8);
        }
#pragma unroll
        for (int ks = 0; ks < 2; ks++) {
            int k0 = ks * 16;
            uint32_t ah[4][4], al[4][4], bh[4][2];
#pragma unroll
            for (int mi = 0; mi < 4; mi++) {
                ldsm_x4(ah[mi], &Ah[wm + mi * 16 + lrow][k0 + lcol]);
                ldsm_x4(al[mi], &Al[wm + mi * 16 + lrow][k0 + lcol]);
            }
#pragma unroll
            for (int nh = 0; nh < 2; nh++) {
                uint32_t r[4];
                ldsm_x4_trans(r, &Bh[k0 + lrow][wn + nh * 16 + lcol]);
                bh[2 * nh][0] = r[0]; bh[2 * nh][1] = r[1];
                bh[2 * nh + 1][0] = r[2]; bh[2 * nh + 1][1] = r[3];
            }
#pragma unroll
            for (int mi = 0; mi < 4; mi++)
#pragma unroll
                for (int ni = 0; ni < 4; ni++) {
                    mma_f16(acc[mi][ni][0], acc[mi][ni][1], acc[mi][ni][2], acc[mi][ni][3],
                            al[mi][0], al[mi][1], al[mi][2], al[mi][3],
                            bh[ni][0], bh[ni][1]);
                    mma_f16(acc[mi][ni][0], acc[mi][ni][1], acc[mi][ni][2], acc[mi][ni][3],
                            ah[mi][0], ah[mi][1], ah[mi][2], ah[mi][3],
                            bh[ni][0], bh[ni][1]);
                }
        }
        __syncthreads();
        if (more) {
            *(uint4*)&Ah[am][kb]      = pah0; *(uint4*)&Ah[am][kb + 8]   = pah1;
            *(uint4*)&Al[am][kb]      = pal0; *(uint4*)&Al[am][kb + 8]   = pal1;
            *(uint4*)&Bh[bkr][bnc]    = pbh0; *(uint4*)&Bh[bkr][bnc + 8] = pbh1;
        }
        __syncthreads();
    }

    // epilogue: gelu -> split -> g_hh/g_hl
#pragma unroll
    for (int mi = 0; mi < 4; mi++) {
        int rm0 = m0 + wm + mi * 16 + group;
        int rm1 = rm0 + 8;
#pragma unroll
        for (int ni = 0; ni < 4; ni++) {
            int n = n0 + wn + ni * 8 + tid4 * 2;
            if (rm0 < cnt) {
                float v0 = gelu_exact(acc[mi][ni][0]);
                float v1 = gelu_exact(acc[mi][ni][1]);
                __half h0, l0, h1, l1;
                f16_split(v0, h0, l0); f16_split(v1, h1, l1);
                size_t o = (size_t)(base + rm0) * FF_DIM + n;
                *(__half2*)(g_hh + o) = __halves2half2(h0, h1);
                *(__half2*)(g_hl + o) = __halves2half2(l0, l1);
            }
            if (rm1 < cnt) {
                float v0 = gelu_exact(acc[mi][ni][2]);
                float v1 = gelu_exact(acc[mi][ni][3]);
                __half h0, l0, h1, l1;
                f16_split(v0, h0, l0); f16_split(v1, h1, l1);
                size_t o = (size_t)(base + rm1) * FF_DIM + n;
                *(__half2*)(g_hh + o) = __halves2half2(h0, h1);
                *(__half2*)(g_hl + o) = __halves2half2(l0, l1);
            }
        }
    }
}

// GEMM2: out[tok(row)] += w(row) * ( h[row] @ w2_e )
__global__ __launch_bounds__(256) void gemm2_kernel(float* __restrict__ out) {
    int e = blockIdx.z;
    int base = g_offsets[e];
    int cnt  = g_counts[e];
    int m0   = blockIdx.y * BM;
    if (m0 >= cnt) return;
    int n0   = blockIdx.x * BN;

    __shared__ __half Ah[BM][AKP], Al[BM][AKP];
    __shared__ __half Bh[BKB][BNP];

    int tid  = threadIdx.x;
    int lane = tid & 31;
    int warp = tid >> 5;
    int group = lane >> 2;
    int tid4  = lane & 3;
    int wm = (warp & 1) * 64;
    int wn = (warp >> 1) * 32;
    int lrow = lane & 15;
    int lcol = (lane >> 4) << 3;

    int am = tid >> 1;
    int kb = (tid & 1) * 16;
    int arow = base + m0 + am;
    if (arow >= NSLOT) arow = NSLOT - 1;
    const __half* aph = g_hh + (size_t)arow * FF_DIM + kb;
    const __half* apl = g_hl + (size_t)arow * FF_DIM + kb;

    int bkr = tid >> 3;
    int bnc = (tid & 7) * 16;
    size_t bbase = (size_t)e * FF_DIM * D_DIM + n0 + bnc;

    float acc[4][4][4];
#pragma unroll
    for (int mi = 0; mi < 4; mi++)
#pragma unroll
        for (int ni = 0; ni < 4; ni++)
#pragma unroll
            for (int c = 0; c < 4; c++) acc[mi][ni][c] = 0.0f;

    uint4 pah0 = *(const uint4*)(aph + 0);
    uint4 pah1 = *(const uint4*)(aph + 8);
    uint4 pal0 = *(const uint4*)(apl + 0);
    uint4 pal1 = *(const uint4*)(apl + 8);
    uint4 pbh0 = *(const uint4*)(g_w2h + (size_t)bkr * D_DIM + bbase);
    uint4 pbh1 = *(const uint4*)(g_w2h + (size_t)bkr * D_DIM + bbase + 8);
    *(uint4*)&Ah[am][kb]     = pah0; *(uint4*)&Ah[am][kb + 8]   = pah1;
    *(uint4*)&Al[am][kb]     = pal0; *(uint4*)&Al[am][kb + 8]   = pal1;
    *(uint4*)&Bh[bkr][bnc]   = pbh0; *(uint4*)&Bh[bkr][bnc + 8] = pbh1;
    __syncthreads();

    for (int kt = 0; kt < FF_DIM; kt += BKB) {
        bool more = (kt + BKB) < FF_DIM;
        if (more) {
            pah0 = *(const uint4*)(aph + kt + BKB + 0);
            pah1 = *(const uint4*)(aph + kt + BKB + 8);
            pal0 = *(const uint4*)(apl + kt + BKB + 0);
            pal1 = *(const uint4*)(apl + kt + BKB + 8);
            pbh0 = *(const uint4*)(g_w2h + (size_t)(kt + BKB + bkr) * D_DIM + bbase);
            pbh1 = *(const uint4*)(g_w2h + (size_t)(kt + BKB + bkr) * D_DIM + bbase + 8);
        }
#pragma unroll
        for (int ks = 0; ks < 2; ks++) {
            int k0 = ks * 16;
            uint32_t ah[4][4], al[4][4], bh[4][2];
#pragma unroll
            for (int mi = 0; mi < 4; mi++) {
                ldsm_x4(ah[mi], &Ah[wm + mi * 16 + lrow][k0 + lcol]);
                ldsm_x4(al[mi], &Al[wm + mi * 16 + lrow][k0 + lcol]);
            }
#pragma unroll
            for (int nh = 0; nh < 2; nh++) {
                uint32_t r[4];
                ldsm_x4_trans(r, &Bh[k0 + lrow][wn + nh * 16 + lcol]);
                bh[2 * nh][0] = r[0]; bh[2 * nh][1] = r[1];
                bh[2 * nh + 1][0] = r[2]; bh[2 * nh + 1][1] = r[3];
            }
#pragma unroll
            for (int mi = 0; mi < 4; mi++)
#pragma unroll
                for (int ni = 0; ni < 4; ni++) {
                    mma_f16(acc[mi][ni][0], acc[mi][ni][1], acc[mi][ni][2], acc[mi][ni][3],
                            al[mi][0], al[mi][1], al[mi][2], al[mi][3],
                            bh[ni][0], bh[ni][1]);
                    mma_f16(acc[mi][ni][0], acc[mi][ni][1], acc[mi][ni][2], acc[mi][ni][3],
                            ah[mi][0], ah[mi][1], ah[mi][2], ah[mi][3],
                            bh[ni][0], bh[ni][1]);
                }
        }
        __syncthreads();
        if (more) {
            *(uint4*)&Ah[am][kb]      = pah0; *(uint4*)&Ah[am][kb + 8]   = pah1;
            *(uint4*)&Al[am][kb]      = pal0; *(uint4*)&Al[am][kb + 8]   = pal1;
            *(uint4*)&Bh[bkr][bnc]    = pbh0; *(uint4*)&Bh[bkr][bnc + 8] = pbh1;
        }
        __syncthreads();
    }

    // epilogue: weighted atomic scatter
#pragma unroll
    for (int mi = 0; mi < 4; mi++) {
        int rm0 = m0 + wm + mi * 16 + group;
        int rm1 = rm0 + 8;
        int r0 = base + rm0, r1 = base + rm1;
        int tok0 = 0, tok1 = 0; float w0 = 0.f, w1v = 0.f;
        if (rm0 < cnt) { tok0 = g_slot_token[r0]; w0 = g_slot_w[r0]; }
        if (rm1 < cnt) { tok1 = g_slot_token[r1]; w1v = g_slot_w[r1]; }
#pragma unroll
        for (int ni = 0; ni < 4; ni++) {
            int n = n0 + wn + ni * 8 + tid4 * 2;
            if (rm0 < cnt) {
                float* op = out + (size_t)tok0 * D_DIM + n;
                atomicAdd(op + 0, w0 * acc[mi][ni][0]);
                atomicAdd(op + 1, w0 * acc[mi][ni][1]);
            }
            if (rm1 < cnt) {
                float* op = out + (size_t)tok1 * D_DIM + n;
                atomicAdd(op + 0, w1v * acc[mi][ni][2]);
                atomicAdd(op + 1, w1v * acc[mi][ni][3]);
            }
        }
    }
}

// ---------------- launcher ----------------
extern "C" void kernel_launch(void* const* d_in, const int* in_sizes, int n_in,
                              void* d_out, int out_size) {
    const float* x  = (const float*)d_in[0];
    const float* rw = (const float*)d_in[1];
    const float* w1 = (const float*)d_in[2];
    const float* w2 = (const float*)d_in[3];
    float* out = (float*)d_out;

    zero_out_kernel<<<1024, 256>>>(out, out_size);
    init_kernel<<<1, 64>>>();
    split_x_kernel<<<2048, 256>>>(x);
    cvt_w1_kernel<<<4096, 256>>>(w1);
    cvt_w2_kernel<<<4096, 256>>>(w2);
    router_kernel<<<T_TOK / 8, 256>>>(x, rw);
    finalize_kernel<<<1, 32>>>(out, out_size);
    scatter_kernel<<<NSLOT / 256, 256>>>();

    dim3 g1(FF_DIM / BN, NSLOT / BM, E_NUM);
    gemm1_kernel<<<g1, 256>>>();
    dim3 g2(D_DIM / BN, NSLOT / BM, E_NUM);
    gemm2_kernel<<<g2, 256>>>(out);
}

// round 10
// speedup vs baseline: 5.2577x; 1.5650x over previous
#include <cuda_runtime.h>
#include <cuda_fp16.h>
#include <math.h>
#include <stdint.h>

// Problem constants
#define T_TOK 8192
#define D_DIM 1024
#define FF_DIM 2048
#define E_NUM 8
#define K_TOP 2
#define NSLOT (T_TOK * K_TOP)
#define W1_LD (E_NUM * FF_DIM)

// ---------------- scratch (device globals) ---------------------------------
__device__ __half g_xh[(size_t)T_TOK * D_DIM];
__device__ __half g_w1h[(size_t)D_DIM * W1_LD];
__device__ __half g_w2h[(size_t)E_NUM * FF_DIM * D_DIM];
__device__ __half g_hh[(size_t)NSLOT * FF_DIM];

__device__ int   g_sel[NSLOT];
__device__ float g_wsel[NSLOT];
__device__ int   g_slot_token[NSLOT];
__device__ float g_slot_w[NSLOT];
__device__ int   g_counts[E_NUM];
__device__ int   g_offsets[E_NUM];
__device__ int   g_fill[E_NUM];
__device__ float g_psum[E_NUM];
__device__ float g_zsum;

// ---------------- convert kernels (f32 -> fp16) ----------------------------
__global__ void cvt_x_kernel(const float* __restrict__ src) {
    int n4 = (T_TOK * D_DIM) / 4;
    const float4* s4 = (const float4*)src;
    for (int i = blockIdx.x * blockDim.x + threadIdx.x; i < n4;
         i += gridDim.x * blockDim.x) {
        float4 v = s4[i];
        __half h[4];
        h[0] = __float2half_rn(v.x); h[1] = __float2half_rn(v.y);
        h[2] = __float2half_rn(v.z); h[3] = __float2half_rn(v.w);
        ((uint2*)g_xh)[i] = *(uint2*)h;
    }
}
__global__ void cvt_w1_kernel(const float* __restrict__ src) {
    int n4 = (D_DIM * W1_LD) / 4;
    const float4* s4 = (const float4*)src;
    for (int i = blockIdx.x * blockDim.x + threadIdx.x; i < n4;
         i += gridDim.x * blockDim.x) {
        float4 v = s4[i];
        __half h[4];
        h[0] = __float2half_rn(v.x); h[1] = __float2half_rn(v.y);
        h[2] = __float2half_rn(v.z); h[3] = __float2half_rn(v.w);
        ((uint2*)g_w1h)[i] = *(uint2*)h;
    }
}
__global__ void cvt_w2_kernel(const float* __restrict__ src) {
    int n4 = (E_NUM * FF_DIM * D_DIM) / 4;
    const float4* s4 = (const float4*)src;
    for (int i = blockIdx.x * blockDim.x + threadIdx.x; i < n4;
         i += gridDim.x * blockDim.x) {
        float4 v = s4[i];
        __half h[4];
        h[0] = __float2half_rn(v.x); h[1] = __float2half_rn(v.y);
        h[2] = __float2half_rn(v.z); h[3] = __float2half_rn(v.w);
        ((uint2*)g_w2h)[i] = *(uint2*)h;
    }
}

// ---------------- kernel 0: zero output ----------------
__global__ void zero_out_kernel(float* out, int n) {
    int idx = blockIdx.x * blockDim.x + threadIdx.x;
    int stride = gridDim.x * blockDim.x;
    for (int i = idx; i < n; i += stride) out[i] = 0.0f;
}

// ---------------- kernel 1: init accumulators ----------------
__global__ void init_kernel() {
    int t = threadIdx.x;
    if (t < E_NUM) { g_counts[t] = 0; g_fill[t] = 0; g_psum[t] = 0.0f; }
    if (t == 0) g_zsum = 0.0f;
}

// ---------------- kernel 2: router ----------------
__global__ __launch_bounds__(256) void router_kernel(
    const float* __restrict__ x, const float* __restrict__ rw)
{
    __shared__ float s_rw[E_NUM * D_DIM];
    __shared__ float sp[E_NUM];
    __shared__ int   sc[E_NUM];
    __shared__ float sz;

    int tid = threadIdx.x;
    for (int i = tid; i < E_NUM * D_DIM; i += 256) s_rw[i] = rw[i];
    if (tid < E_NUM) { sp[tid] = 0.0f; sc[tid] = 0; }
    if (tid == 0) sz = 0.0f;
    __syncthreads();

    int warp = tid >> 5;
    int lane = tid & 31;
    int t = blockIdx.x * 8 + warp;

    float acc[E_NUM];
#pragma unroll
    for (int e = 0; e < E_NUM; e++) acc[e] = 0.0f;

    const float* xr = x + (size_t)t * D_DIM;
    for (int d = lane; d < D_DIM; d += 32) {
        float xv = xr[d];
#pragma unroll
        for (int e = 0; e < E_NUM; e++) acc[e] += xv * s_rw[e * D_DIM + d];
    }
#pragma unroll
    for (int e = 0; e < E_NUM; e++) {
#pragma unroll
        for (int off = 16; off > 0; off >>= 1)
            acc[e] += __shfl_xor_sync(0xFFFFFFFF, acc[e], off);
    }

    if (lane == 0) {
        float m = acc[0];
#pragma unroll
        for (int e = 1; e < E_NUM; e++) m = fmaxf(m, acc[e]);
        float p[E_NUM], s = 0.0f;
#pragma unroll
        for (int e = 0; e < E_NUM; e++) { p[e] = expf(acc[e] - m); s += p[e]; }
        float inv = 1.0f / s;
        float lse = m + logf(s);

        int i1 = 0;
#pragma unroll
        for (int e = 1; e < E_NUM; e++) if (acc[e] > acc[i1]) i1 = e;
        int i2 = (i1 == 0) ? 1 : 0;
#pragma unroll
        for (int e = 0; e < E_NUM; e++)
            if (e != i1 && acc[e] > acc[i2]) i2 = e;

        float p1 = p[i1] * inv, p2 = p[i2] * inv;
        float winv = 1.0f / (p1 + p2);
        g_sel[2 * t]      = i1;
        g_wsel[2 * t]     = p1 * winv;
        g_sel[2 * t + 1]  = i2;
        g_wsel[2 * t + 1] = p2 * winv;

#pragma unroll
        for (int e = 0; e < E_NUM; e++) atomicAdd(&sp[e], p[e] * inv);
        atomicAdd(&sz, lse * lse);
        atomicAdd(&sc[i1], 1);
        atomicAdd(&sc[i2], 1);
    }
    __syncthreads();
    if (tid < E_NUM) {
        atomicAdd(&g_psum[tid], sp[tid]);
        atomicAdd(&g_counts[tid], sc[tid]);
    }
    if (tid == 0) atomicAdd(&g_zsum, sz);
}

// ---------------- kernel 3: finalize losses + offsets scan ----------------
__global__ void finalize_kernel(float* out, int out_size) {
    if (threadIdx.x == 0 && blockIdx.x == 0) {
        int off = 0;
        for (int e = 0; e < E_NUM; e++) { g_offsets[e] = off; off += g_counts[e]; }
        float z = g_zsum / (float)T_TOK;
        float lb = 0.0f;
        for (int e = 0; e < E_NUM; e++)
            lb += ((float)g_counts[e] / (float)(T_TOK * K_TOP)) *
                  (g_psum[e] / (float)T_TOK);
        lb *= (float)E_NUM;
        out[out_size - 2] = z;
        out[out_size - 1] = lb;
    }
}

// ---------------- kernel 4: scatter into expert groups ----------------
__global__ void scatter_kernel() {
    int s = blockIdx.x * blockDim.x + threadIdx.x;
    if (s >= NSLOT) return;
    int e = g_sel[s];
    int pos = g_offsets[e] + atomicAdd(&g_fill[e], 1);
    g_slot_token[pos] = s >> 1;
    g_slot_w[pos]     = g_wsel[s];
}

// ============== fp16 tensor-core grouped GEMMs =============================
// Tile BM=128, BN=128, BK=32. 256 thr = 8 warps (2M x 4N), warp 64x32.
// mma.m16n8k16.f16, fp32 accumulate, single limb both sides.
#define BM 128
#define BN 128
#define BKB 32
#define AKP 40    // A row stride (half): 80 B
#define BNP 136   // B row stride (half): 272 B

__device__ __forceinline__ float gelu_exact(float v) {
    return 0.5f * v * (1.0f + erff(v * 0.70710678118654752f));
}

__device__ __forceinline__ void mma_f16(
    float& c0, float& c1, float& c2, float& c3,
    uint32_t a0, uint32_t a1, uint32_t a2, uint32_t a3,
    uint32_t b0, uint32_t b1)
{
    asm volatile(
        "mma.sync.aligned.m16n8k16.row.col.f32.f16.f16.f32 "
        "{%0,%1,%2,%3}, {%4,%5,%6,%7}, {%8,%9}, {%0,%1,%2,%3};"
        : "+f"(c0), "+f"(c1), "+f"(c2), "+f"(c3)
        : "r"(a0), "r"(a1), "r"(a2), "r"(a3), "r"(b0), "r"(b1));
}

__device__ __forceinline__ void ldsm_x4(uint32_t* r, const void* p) {
    uint32_t addr = (uint32_t)__cvta_generic_to_shared(p);
    asm volatile("ldmatrix.sync.aligned.m8n8.x4.shared.b16 {%0,%1,%2,%3}, [%4];"
                 : "=r"(r[0]), "=r"(r[1]), "=r"(r[2]), "=r"(r[3]) : "r"(addr));
}
__device__ __forceinline__ void ldsm_x4_trans(uint32_t* r, const void* p) {
    uint32_t addr = (uint32_t)__cvta_generic_to_shared(p);
    asm volatile("ldmatrix.sync.aligned.m8n8.x4.trans.shared.b16 {%0,%1,%2,%3}, [%4];"
                 : "=r"(r[0]), "=r"(r[1]), "=r"(r[2]), "=r"(r[3]) : "r"(addr));
}

// GEMM1: h = gelu( x_gathered @ w1_e )   [slots x FF]
__global__ __launch_bounds__(256, 2) void gemm1_kernel() {
    int e = blockIdx.z;
    int base = g_offsets[e];
    int cnt  = g_counts[e];
    int m0   = blockIdx.y * BM;
    if (m0 >= cnt) return;
    int n0   = blockIdx.x * BN;

    __shared__ __half Ah[BM][AKP];
    __shared__ __half Bh[BKB][BNP];

    int tid  = threadIdx.x;
    int lane = tid & 31;
    int warp = tid >> 5;
    int group = lane >> 2;
    int tid4  = lane & 3;
    int wm = (warp & 1) * 64;
    int wn = (warp >> 1) * 32;
    int lrow = lane & 15;
    int lcol = (lane >> 4) << 3;

    int am = tid >> 1;
    int kb = (tid & 1) * 16;
    int arow = base + m0 + am;
    int tok  = g_slot_token[arow < NSLOT ? arow : NSLOT - 1];
    const __half* aph = g_xh + (size_t)tok * D_DIM + kb;

    int bkr = tid >> 3;
    int bnc = (tid & 7) * 16;
    size_t bbase = (size_t)e * FF_DIM + n0 + bnc;

    float acc[4][4][4];
#pragma unroll
    for (int mi = 0; mi < 4; mi++)
#pragma unroll
        for (int ni = 0; ni < 4; ni++)
#pragma unroll
            for (int c = 0; c < 4; c++) acc[mi][ni][c] = 0.0f;

    uint4 pah0 = *(const uint4*)(aph + 0);
    uint4 pah1 = *(const uint4*)(aph + 8);
    uint4 pbh0 = *(const uint4*)(g_w1h + (size_t)bkr * W1_LD + bbase);
    uint4 pbh1 = *(const uint4*)(g_w1h + (size_t)bkr * W1_LD + bbase + 8);
    *(uint4*)&Ah[am][kb]     = pah0; *(uint4*)&Ah[am][kb + 8]   = pah1;
    *(uint4*)&Bh[bkr][bnc]   = pbh0; *(uint4*)&Bh[bkr][bnc + 8] = pbh1;
    __syncthreads();

    for (int kt = 0; kt < D_DIM; kt += BKB) {
        bool more = (kt + BKB) < D_DIM;
        if (more) {
            pah0 = *(const uint4*)(aph + kt + BKB + 0);
            pah1 = *(const uint4*)(aph + kt + BKB + 8);
            pbh0 = *(const uint4*)(g_w1h + (size_t)(kt + BKB + bkr) * W1_LD + bbase);
            pbh1 = *(const uint4*)(g_w1h + (size_t)(kt + BKB + bkr) * W1_LD + bbase + 8);
        }
#pragma unroll
        for (int ks = 0; ks < 2; ks++) {
            int k0 = ks * 16;
            uint32_t ah[4][4], bh[4][2];
#pragma unroll
            for (int mi = 0; mi < 4; mi++)
                ldsm_x4(ah[mi], &Ah[wm + mi * 16 + lrow][k0 + lcol]);
#pragma unroll
            for (int nh = 0; nh < 2; nh++) {
                uint32_t r[4];
                ldsm_x4_trans(r, &Bh[k0 + lrow][wn + nh * 16 + lcol]);
                bh[2 * nh][0] = r[0]; bh[2 * nh][1] = r[1];
                bh[2 * nh + 1][0] = r[2]; bh[2 * nh + 1][1] = r[3];
            }
#pragma unroll
            for (int mi = 0; mi < 4; mi++)
#pragma unroll
                for (int ni = 0; ni < 4; ni++)
                    mma_f16(acc[mi][ni][0], acc[mi][ni][1], acc[mi][ni][2], acc[mi][ni][3],
                            ah[mi][0], ah[mi][1], ah[mi][2], ah[mi][3],
                            bh[ni][0], bh[ni][1]);
        }
        __syncthreads();
        if (more) {
            *(uint4*)&Ah[am][kb]      = pah0; *(uint4*)&Ah[am][kb + 8]   = pah1;
            *(uint4*)&Bh[bkr][bnc]    = pbh0; *(uint4*)&Bh[bkr][bnc + 8] = pbh1;
        }
        __syncthreads();
    }

    // epilogue: gelu -> fp16 -> g_hh
#pragma unroll
    for (int mi = 0; mi < 4; mi++) {
        int rm0 = m0 + wm + mi * 16 + group;
        int rm1 = rm0 + 8;
#pragma unroll
        for (int ni = 0; ni < 4; ni++) {
            int n = n0 + wn + ni * 8 + tid4 * 2;
            if (rm0 < cnt) {
                __half h0 = __float2half_rn(gelu_exact(acc[mi][ni][0]));
                __half h1 = __float2half_rn(gelu_exact(acc[mi][ni][1]));
                *(__half2*)(g_hh + (size_t)(base + rm0) * FF_DIM + n) =
                    __halves2half2(h0, h1);
            }
            if (rm1 < cnt) {
                __half h0 = __float2half_rn(gelu_exact(acc[mi][ni][2]));
                __half h1 = __float2half_rn(gelu_exact(acc[mi][ni][3]));
                *(__half2*)(g_hh + (size_t)(base + rm1) * FF_DIM + n) =
                    __halves2half2(h0, h1);
            }
        }
    }
}

// GEMM2: out[tok(row)] += w(row) * ( h[row] @ w2_e )
__global__ __launch_bounds__(256, 2) void gemm2_kernel(float* __restrict__ out) {
    int e = blockIdx.z;
    int base = g_offsets[e];
    int cnt  = g_counts[e];
    int m0   = blockIdx.y * BM;
    if (m0 >= cnt) return;
    int n0   = blockIdx.x * BN;

    __shared__ __half Ah[BM][AKP];
    __shared__ __half Bh[BKB][BNP];

    int tid  = threadIdx.x;
    int lane = tid & 31;
    int warp = tid >> 5;
    int group = lane >> 2;
    int tid4  = lane & 3;
    int wm = (warp & 1) * 64;
    int wn = (warp >> 1) * 32;
    int lrow = lane & 15;
    int lcol = (lane >> 4) << 3;

    int am = tid >> 1;
    int kb = (tid & 1) * 16;
    int arow = base + m0 + am;
    if (arow >= NSLOT) arow = NSLOT - 1;
    const __half* aph = g_hh + (size_t)arow * FF_DIM + kb;

    int bkr = tid >> 3;
    int bnc = (tid & 7) * 16;
    size_t bbase = (size_t)e * FF_DIM * D_DIM + n0 + bnc;

    float acc[4][4][4];
#pragma unroll
    for (int mi = 0; mi < 4; mi++)
#pragma unroll
        for (int ni = 0; ni < 4; ni++)
#pragma unroll
            for (int c = 0; c < 4; c++) acc[mi][ni][c] = 0.0f;

    uint4 pah0 = *(const uint4*)(aph + 0);
    uint4 pah1 = *(const uint4*)(aph + 8);
    uint4 pbh0 = *(const uint4*)(g_w2h + (size_t)bkr * D_DIM + bbase);
    uint4 pbh1 = *(const uint4*)(g_w2h + (size_t)bkr * D_DIM + bbase + 8);
    *(uint4*)&Ah[am][kb]     = pah0; *(uint4*)&Ah[am][kb + 8]   = pah1;
    *(uint4*)&Bh[bkr][bnc]   = pbh0; *(uint4*)&Bh[bkr][bnc + 8] = pbh1;
    __syncthreads();

    for (int kt = 0; kt < FF_DIM; kt += BKB) {
        bool more = (kt + BKB) < FF_DIM;
        if (more) {
            pah0 = *(const uint4*)(aph + kt + BKB + 0);
            pah1 = *(const uint4*)(aph + kt + BKB + 8);
            pbh0 = *(const uint4*)(g_w2h + (size_t)(kt + BKB + bkr) * D_DIM + bbase);
            pbh1 = *(const uint4*)(g_w2h + (size_t)(kt + BKB + bkr) * D_DIM + bbase + 8);
        }
#pragma unroll
        for (int ks = 0; ks < 2; ks++) {
            int k0 = ks * 16;
            uint32_t ah[4][4], bh[4][2];
#pragma unroll
            for (int mi = 0; mi < 4; mi++)
                ldsm_x4(ah[mi], &Ah[wm + mi * 16 + lrow][k0 + lcol]);
#pragma unroll
            for (int nh = 0; nh < 2; nh++) {
                uint32_t r[4];
                ldsm_x4_trans(r, &Bh[k0 + lrow][wn + nh * 16 + lcol]);
                bh[2 * nh][0] = r[0]; bh[2 * nh][1] = r[1];
                bh[2 * nh + 1][0] = r[2]; bh[2 * nh + 1][1] = r[3];
            }
#pragma unroll
            for (int mi = 0; mi < 4; mi++)
#pragma unroll
                for (int ni = 0; ni < 4; ni++)
                    mma_f16(acc[mi][ni][0], acc[mi][ni][1], acc[mi][ni][2], acc[mi][ni][3],
                            ah[mi][0], ah[mi][1], ah[mi][2], ah[mi][3],
                            bh[ni][0], bh[ni][1]);
        }
        __syncthreads();
        if (more) {
            *(uint4*)&Ah[am][kb]      = pah0; *(uint4*)&Ah[am][kb + 8]   = pah1;
            *(uint4*)&Bh[bkr][bnc]    = pbh0; *(uint4*)&Bh[bkr][bnc + 8] = pbh1;
        }
        __syncthreads();
    }

    // epilogue: weighted atomic scatter
#pragma unroll
    for (int mi = 0; mi < 4; mi++) {
        int rm0 = m0 + wm + mi * 16 + group;
        int rm1 = rm0 + 8;
        int r0 = base + rm0, r1 = base + rm1;
        int tok0 = 0, tok1 = 0; float w0 = 0.f, w1v = 0.f;
        if (rm0 < cnt) { tok0 = g_slot_token[r0]; w0 = g_slot_w[r0]; }
        if (rm1 < cnt) { tok1 = g_slot_token[r1]; w1v = g_slot_w[r1]; }
#pragma unroll
        for (int ni = 0; ni < 4; ni++) {
            int n = n0 + wn + ni * 8 + tid4 * 2;
            if (rm0 < cnt) {
                float* op = out + (size_t)tok0 * D_DIM + n;
                atomicAdd(op + 0, w0 * acc[mi][ni][0]);
                atomicAdd(op + 1, w0 * acc[mi][ni][1]);
            }
            if (rm1 < cnt) {
                float* op = out + (size_t)tok1 * D_DIM + n;
                atomicAdd(op + 0, w1v * acc[mi][ni][2]);
                atomicAdd(op + 1, w1v * acc[mi][ni][3]);
            }
        }
    }
}

// ---------------- launcher ----------------
extern "C" void kernel_launch(void* const* d_in, const int* in_sizes, int n_in,
                              void* d_out, int out_size) {
    const float* x  = (const float*)d_in[0];
    const float* rw = (const float*)d_in[1];
    const float* w1 = (const float*)d_in[2];
    const float* w2 = (const float*)d_in[3];
    float* out = (float*)d_out;

    zero_out_kernel<<<1024, 256>>>(out, out_size);
    init_kernel<<<1, 64>>>();
    cvt_x_kernel<<<2048, 256>>>(x);
    cvt_w1_kernel<<<4096, 256>>>(w1);
    cvt_w2_kernel<<<4096, 256>>>(w2);
    router_kernel<<<T_TOK / 8, 256>>>(x, rw);
    finalize_kernel<<<1, 32>>>(out, out_size);
    scatter_kernel<<<NSLOT / 256, 256>>>();

    dim3 g1(FF_DIM / BN, NSLOT / BM, E_NUM);
    gemm1_kernel<<<g1, 256>>>();
    dim3 g2(D_DIM / BN, NSLOT / BM, E_NUM);
    gemm2_kernel<<<g2, 256>>>(out);
}